// round 1
// baseline (speedup 1.0000x reference)
#include <cuda_runtime.h>
#include <cuda_bf16.h>
#include <cstdint>

// Problem dims
#define S_LEN 4096
#define D_DIM 2048
#define H_NUM 16
#define HD_DIM 128
#define F_DIM 8192

// ---------------------------------------------------------------------------
// Scratch (allocation is banned; use device globals)
// ---------------------------------------------------------------------------
__device__ float g_q[S_LEN * D_DIM];
__device__ float g_k[S_LEN * D_DIM];
__device__ float g_v[S_LEN * D_DIM];
__device__ float g_heads[S_LEN * D_DIM];
__device__ float g_proj[S_LEN * D_DIM];
__device__ float g_ln[S_LEN * D_DIM];
__device__ float g_h1[S_LEN * F_DIM];

// ---------------------------------------------------------------------------
// Generic tiled SGEMM: C[M,N] = A[M,K] @ B + epilogue
//   BMODE 0: B row-major [K,N]
//   BMODE 1: B head-stacked [H, K, 128], logical n = h*128 + e
//   EPI 0: + bias[n]
//   EPI 1: + bias[n] + res[m,n]
//   EPI 2: relu(+ bias[n])
// Block tile 128x128, K-tile 8, 256 threads, 8x8 per-thread tile.
// M,N multiples of 128; K multiple of 8 (all true here).
// ---------------------------------------------------------------------------
template <int BMODE, int EPI>
__global__ void __launch_bounds__(256) sgemm_kernel(
    const float* __restrict__ A, const float* __restrict__ B,
    const float* __restrict__ bias, const float* __restrict__ res,
    float* __restrict__ C, int M, int N, int K)
{
    __shared__ float As[8][132];
    __shared__ float Bs[8][132];

    const int tid = threadIdx.x;
    const int tx = tid & 15;
    const int ty = tid >> 4;
    const int bn = blockIdx.x * 128;
    const int bm = blockIdx.y * 128;

    const int arow = tid >> 1;         // 0..127
    const int acol = (tid & 1) * 4;    // 0 or 4
    const int brow = tid >> 5;         // 0..7
    const int bcol = (tid & 31) * 4;   // 0..124

    const float* Ap = A + (size_t)(bm + arow) * K + acol;

    size_t bbase;
    if (BMODE == 0) {
        bbase = (size_t)brow * N + bn + bcol;
    } else {
        int n = bn + bcol;             // BN=128 -> whole tile is one head
        bbase = ((size_t)(n >> 7) * K + brow) * 128 + (n & 127);
    }
    const size_t bstep = (BMODE == 0) ? (size_t)8 * N : (size_t)8 * 128;

    float acc[8][8];
#pragma unroll
    for (int i = 0; i < 8; i++)
#pragma unroll
        for (int j = 0; j < 8; j++) acc[i][j] = 0.f;

    for (int k0 = 0; k0 < K; k0 += 8) {
        float4 av = *(const float4*)(Ap + k0);
        float4 bv = *(const float4*)(B + bbase);
        bbase += bstep;

        As[acol + 0][arow] = av.x;
        As[acol + 1][arow] = av.y;
        As[acol + 2][arow] = av.z;
        As[acol + 3][arow] = av.w;
        *(float4*)&Bs[brow][bcol] = bv;
        __syncthreads();

#pragma unroll
        for (int kk = 0; kk < 8; kk++) {
            float a[8], b[8];
            *(float4*)&a[0] = *(const float4*)&As[kk][ty * 8];
            *(float4*)&a[4] = *(const float4*)&As[kk][ty * 8 + 4];
            *(float4*)&b[0] = *(const float4*)&Bs[kk][tx * 8];
            *(float4*)&b[4] = *(const float4*)&Bs[kk][tx * 8 + 4];
#pragma unroll
            for (int i = 0; i < 8; i++)
#pragma unroll
                for (int j = 0; j < 8; j++) acc[i][j] += a[i] * b[j];
        }
        __syncthreads();
    }

    // epilogue
#pragma unroll
    for (int i = 0; i < 8; i++) {
        const int m = bm + ty * 8 + i;
#pragma unroll
        for (int j0 = 0; j0 < 8; j0 += 4) {
            const int n = bn + tx * 8 + j0;
            float4 bv = *(const float4*)(bias + n);
            float4 v;
            v.x = acc[i][j0 + 0] + bv.x;
            v.y = acc[i][j0 + 1] + bv.y;
            v.z = acc[i][j0 + 2] + bv.z;
            v.w = acc[i][j0 + 3] + bv.w;
            if (EPI == 1) {
                float4 rv = *(const float4*)(res + (size_t)m * N + n);
                v.x += rv.x; v.y += rv.y; v.z += rv.z; v.w += rv.w;
            }
            if (EPI == 2) {
                v.x = fmaxf(v.x, 0.f); v.y = fmaxf(v.y, 0.f);
                v.z = fmaxf(v.z, 0.f); v.w = fmaxf(v.w, 0.f);
            }
            *(float4*)(C + (size_t)m * N + n) = v;
        }
    }
}

// ---------------------------------------------------------------------------
// Flash attention, fp32, full (non-causal) attention.
// q/k/v layout: [S, H*HD] row-major (n = h*128 + e). Output heads same layout.
// Block = (qblock of 64 rows, one head). 256 threads.
// ---------------------------------------------------------------------------
#define FA_SMEM_FLOATS (3 * 64 * 132 + 64 * 68 + 3 * 64)

__global__ void __launch_bounds__(256) flash_attn_kernel(
    const float* __restrict__ qb, const float* __restrict__ kb,
    const float* __restrict__ vb, float* __restrict__ heads)
{
    extern __shared__ float sm[];
    float* Qs = sm;                    // 64 x 132 (128 used)
    float* Ks = Qs + 64 * 132;
    float* Vs = Ks + 64 * 132;
    float* Ss = Vs + 64 * 132;         // 64 x 68 (64 used)
    float* m_s  = Ss + 64 * 68;        // 64
    float* l_s  = m_s + 64;            // 64
    float* al_s = l_s + 64;            // 64

    const int h   = blockIdx.y;
    const int q0  = blockIdx.x * 64;
    const int tid = threadIdx.x;
    const float scale = 0.08838834764831845f;  // 1/sqrt(128)

    // load Q tile
    {
        int idx = tid * 4;
#pragma unroll
        for (int it = 0; it < 8; ++it) {
            int r = idx >> 7, c = idx & 127;
            *(float4*)(Qs + r * 132 + c) =
                *(const float4*)(qb + (size_t)(q0 + r) * D_DIM + h * 128 + c);
            idx += 1024;
        }
    }
    if (tid < 64) { m_s[tid] = -1e30f; l_s[tid] = 0.f; al_s[tid] = 0.f; }

    float O[8][4];
#pragma unroll
    for (int i = 0; i < 8; i++)
#pragma unroll
        for (int c = 0; c < 4; c++) O[i][c] = 0.f;

    const int oty = tid >> 5;   // 0..7   -> O rows oty*8 .. +7
    const int otx = tid & 31;   //        -> O cols otx + 32*c
    const int sty = tid >> 4;   // 0..15  -> S rows sty*4 .. +3
    const int stx = tid & 15;   //        -> S cols stx*4 .. +3
    const int srow = tid >> 2;  // 0..63  softmax row
    const int sq   = tid & 3;   // 16 cols each

    for (int kblk = 0; kblk < 64; ++kblk) {
        __syncthreads();  // Ks/Vs/Ss free (also publishes Qs on first iter)

        // load K and V tiles
        {
            int idx = tid * 4;
#pragma unroll
            for (int it = 0; it < 8; ++it) {
                int r = idx >> 7, c = idx & 127;
                size_t g = (size_t)(kblk * 64 + r) * D_DIM + h * 128 + c;
                *(float4*)(Ks + r * 132 + c) = *(const float4*)(kb + g);
                *(float4*)(Vs + r * 132 + c) = *(const float4*)(vb + g);
                idx += 1024;
            }
        }
        __syncthreads();

        // S = scale * Q @ K^T   (4x4 per thread)
        {
            float acc[4][4];
#pragma unroll
            for (int i = 0; i < 4; i++)
#pragma unroll
                for (int j = 0; j < 4; j++) acc[i][j] = 0.f;
#pragma unroll 4
            for (int e = 0; e < 128; ++e) {
                float qv[4], kv[4];
#pragma unroll
                for (int i = 0; i < 4; i++) qv[i] = Qs[(sty * 4 + i) * 132 + e];
#pragma unroll
                for (int j = 0; j < 4; j++) kv[j] = Ks[(stx * 4 + j) * 132 + e];
#pragma unroll
                for (int i = 0; i < 4; i++)
#pragma unroll
                    for (int j = 0; j < 4; j++) acc[i][j] += qv[i] * kv[j];
            }
#pragma unroll
            for (int i = 0; i < 4; i++)
#pragma unroll
                for (int j = 0; j < 4; j++)
                    Ss[(sty * 4 + i) * 68 + stx * 4 + j] = acc[i][j] * scale;
        }
        __syncthreads();

        // online softmax per row (4 threads per row)
        {
            float sv[16];
            float mx = -1e30f;
#pragma unroll
            for (int c = 0; c < 16; c++) {
                sv[c] = Ss[srow * 68 + sq * 16 + c];
                mx = fmaxf(mx, sv[c]);
            }
            mx = fmaxf(mx, __shfl_xor_sync(0xffffffffu, mx, 1));
            mx = fmaxf(mx, __shfl_xor_sync(0xffffffffu, mx, 2));
            const float m_old = m_s[srow];
            const float m_new = fmaxf(m_old, mx);
            float lsum = 0.f;
#pragma unroll
            for (int c = 0; c < 16; c++) {
                float p = __expf(sv[c] - m_new);
                Ss[srow * 68 + sq * 16 + c] = p;
                lsum += p;
            }
            lsum += __shfl_xor_sync(0xffffffffu, lsum, 1);
            lsum += __shfl_xor_sync(0xffffffffu, lsum, 2);
            if (sq == 0) {
                float alpha = __expf(m_old - m_new);
                l_s[srow] = l_s[srow] * alpha + lsum;
                m_s[srow] = m_new;
                al_s[srow] = alpha;
            }
        }
        __syncthreads();

        // O = O*alpha + P @ V   (8 rows x 4 cols per thread)
#pragma unroll
        for (int i = 0; i < 8; i++) {
            const float alpha = al_s[oty * 8 + i];
#pragma unroll
            for (int c = 0; c < 4; c++) O[i][c] *= alpha;
        }
        for (int j = 0; j < 64; ++j) {
            float vv[4];
#pragma unroll
            for (int c = 0; c < 4; c++) vv[c] = Vs[j * 132 + otx + 32 * c];
#pragma unroll
            for (int i = 0; i < 8; i++) {
                const float p = Ss[(oty * 8 + i) * 68 + j];
#pragma unroll
                for (int c = 0; c < 4; c++) O[i][c] += p * vv[c];
            }
        }
    }
    __syncthreads();

    // normalize and write heads[s, h*128 + c]
#pragma unroll
    for (int i = 0; i < 8; i++) {
        const int r = oty * 8 + i;
        const float inv = 1.f / l_s[r];
#pragma unroll
        for (int c = 0; c < 4; c++) {
            heads[(size_t)(q0 + r) * D_DIM + h * 128 + otx + 32 * c] = O[i][c] * inv;
        }
    }
}

// ---------------------------------------------------------------------------
// LayerNorm over D=2048 per row (population variance, eps=1e-5)
// ---------------------------------------------------------------------------
__global__ void __launch_bounds__(256) layernorm_kernel(
    const float* __restrict__ in, const float* __restrict__ gamma,
    const float* __restrict__ beta, float* __restrict__ out)
{
    __shared__ float red[16];
    const int row = blockIdx.x;
    const int tid = threadIdx.x;
    const float* rp = in + (size_t)row * D_DIM;

    float v[8];
    float s = 0.f, sq = 0.f;
#pragma unroll
    for (int it = 0; it < 2; ++it) {
        float4 t = *(const float4*)(rp + tid * 4 + it * 1024);
        v[it * 4 + 0] = t.x; v[it * 4 + 1] = t.y;
        v[it * 4 + 2] = t.z; v[it * 4 + 3] = t.w;
    }
#pragma unroll
    for (int i = 0; i < 8; i++) { s += v[i]; sq += v[i] * v[i]; }
#pragma unroll
    for (int o = 16; o > 0; o >>= 1) {
        s  += __shfl_xor_sync(0xffffffffu, s, o);
        sq += __shfl_xor_sync(0xffffffffu, sq, o);
    }
    if ((tid & 31) == 0) { red[tid >> 5] = s; red[8 + (tid >> 5)] = sq; }
    __syncthreads();
    if (tid < 32) {
        float ss = (tid < 8) ? red[tid] : 0.f;
        float qq = (tid < 8) ? red[8 + tid] : 0.f;
#pragma unroll
        for (int o = 4; o > 0; o >>= 1) {
            ss += __shfl_xor_sync(0xffffffffu, ss, o);
            qq += __shfl_xor_sync(0xffffffffu, qq, o);
        }
        if (tid == 0) { red[0] = ss; red[1] = qq; }
    }
    __syncthreads();
    const float mu  = red[0] * (1.f / D_DIM);
    const float var = red[1] * (1.f / D_DIM) - mu * mu;
    const float rs  = rsqrtf(var + 1e-5f);
#pragma unroll
    for (int it = 0; it < 2; ++it) {
        const int c = tid * 4 + it * 1024;
        float4 g = *(const float4*)(gamma + c);
        float4 b = *(const float4*)(beta + c);
        float4 o;
        o.x = (v[it * 4 + 0] - mu) * rs * g.x + b.x;
        o.y = (v[it * 4 + 1] - mu) * rs * g.y + b.y;
        o.z = (v[it * 4 + 2] - mu) * rs * g.z + b.z;
        o.w = (v[it * 4 + 3] - mu) * rs * g.w + b.w;
        *(float4*)(out + (size_t)row * D_DIM + c) = o;
    }
}

// ---------------------------------------------------------------------------
// Launch
// ---------------------------------------------------------------------------
extern "C" void kernel_launch(void* const* d_in, const int* in_sizes, int n_in,
                              void* d_out, int out_size)
{
    const float* x     = (const float*)d_in[0];
    const float* Wq    = (const float*)d_in[1];
    const float* bq    = (const float*)d_in[2];
    const float* Wk    = (const float*)d_in[3];
    const float* bk    = (const float*)d_in[4];
    const float* Wv    = (const float*)d_in[5];
    const float* bv    = (const float*)d_in[6];
    const float* Wp    = (const float*)d_in[7];
    const float* bp    = (const float*)d_in[8];
    const float* W1    = (const float*)d_in[9];
    const float* b1    = (const float*)d_in[10];
    const float* W2    = (const float*)d_in[11];
    const float* b2    = (const float*)d_in[12];
    const float* gamma = (const float*)d_in[13];
    const float* beta  = (const float*)d_in[14];
    float* out = (float*)d_out;

    float *q, *k, *v, *heads, *proj, *ln, *h1;
    cudaGetSymbolAddress((void**)&q,     g_q);
    cudaGetSymbolAddress((void**)&k,     g_k);
    cudaGetSymbolAddress((void**)&v,     g_v);
    cudaGetSymbolAddress((void**)&heads, g_heads);
    cudaGetSymbolAddress((void**)&proj,  g_proj);
    cudaGetSymbolAddress((void**)&ln,    g_ln);
    cudaGetSymbolAddress((void**)&h1,    g_h1);

    const dim3 blk(256);
    const dim3 grid_dd(D_DIM / 128, S_LEN / 128);   // 16 x 32
    const dim3 grid_f1(F_DIM / 128, S_LEN / 128);   // 64 x 32

    // QKV projections (head-stacked B, bias epilogue)
    sgemm_kernel<1, 0><<<grid_dd, blk>>>(x, Wq, bq, nullptr, q, S_LEN, D_DIM, D_DIM);
    sgemm_kernel<1, 0><<<grid_dd, blk>>>(x, Wk, bk, nullptr, k, S_LEN, D_DIM, D_DIM);
    sgemm_kernel<1, 0><<<grid_dd, blk>>>(x, Wv, bv, nullptr, v, S_LEN, D_DIM, D_DIM);

    // Flash attention
    const int fa_smem = FA_SMEM_FLOATS * (int)sizeof(float);
    cudaFuncSetAttribute(flash_attn_kernel,
                         cudaFuncAttributeMaxDynamicSharedMemorySize, fa_smem);
    flash_attn_kernel<<<dim3(S_LEN / 64, H_NUM), blk, fa_smem>>>(q, k, v, heads);

    // Output projection + residual, then LayerNorm
    sgemm_kernel<0, 1><<<grid_dd, blk>>>(heads, Wp, bp, x, proj, S_LEN, D_DIM, D_DIM);
    layernorm_kernel<<<S_LEN, blk>>>(proj, gamma, beta, ln);

    // FFN
    sgemm_kernel<0, 2><<<grid_f1, blk>>>(ln, W1, b1, nullptr, h1, S_LEN, F_DIM, D_DIM);
    sgemm_kernel<0, 0><<<grid_dd, blk>>>(h1, W2, b2, nullptr, out, S_LEN, D_DIM, F_DIM);
}

// round 3
// speedup vs baseline: 1.4693x; 1.4693x over previous
#include <cuda_runtime.h>
#include <cstdint>

// Problem dims
#define S_LEN 4096
#define D_DIM 2048
#define H_NUM 16
#define F_DIM 8192

// ---------------------------------------------------------------------------
// Scratch (allocation is banned; use device globals)
// ---------------------------------------------------------------------------
__device__ float g_q[S_LEN * D_DIM];
__device__ float g_k[S_LEN * D_DIM];
__device__ float g_v[S_LEN * D_DIM];
__device__ float g_heads[S_LEN * D_DIM];
__device__ float g_proj[S_LEN * D_DIM];
__device__ float g_ln[S_LEN * D_DIM];
__device__ float g_h1[S_LEN * F_DIM];
// transposed weights, [N, K] row-major
__device__ float g_wqt[D_DIM * D_DIM];
__device__ float g_wkt[D_DIM * D_DIM];
__device__ float g_wvt[D_DIM * D_DIM];
__device__ float g_wpt[D_DIM * D_DIM];
__device__ float g_w1t[F_DIM * D_DIM];
__device__ float g_w2t[D_DIM * F_DIM];

// ---------------------------------------------------------------------------
// tf32 helpers (sm_80+ instructions only — harness PTX targets plain sm_103,
// so tcgen05/sm_103a-gated instructions are unusable; mma.sync is portable)
// ---------------------------------------------------------------------------
__device__ __forceinline__ float cvt_tf32(float x) {
    float y;
    asm("cvt.rna.tf32.f32 %0, %1;" : "=f"(y) : "f"(x));
    return y;
}

__device__ __forceinline__ void mma_tf32(float* c, const uint32_t* a, const uint32_t* b) {
    asm volatile(
        "mma.sync.aligned.m16n8k8.row.col.f32.tf32.tf32.f32 "
        "{%0,%1,%2,%3}, {%4,%5,%6,%7}, {%8,%9}, {%0,%1,%2,%3};"
        : "+f"(c[0]), "+f"(c[1]), "+f"(c[2]), "+f"(c[3])
        : "r"(a[0]), "r"(a[1]), "r"(a[2]), "r"(a[3]), "r"(b[0]), "r"(b[1]));
}

// ---------------------------------------------------------------------------
// tf32 warp-MMA GEMM: C[M,N] = A[M,K] @ Bt[N,K]^T + epilogue
// CTA tile 128x128, BK=32, 256 threads = 8 warps (2Mx4N), warp tile 64x32.
// Double-buffered smem, padded stride 36 floats.
//   EPI 0: +bias   EPI 1: +bias+res   EPI 2: relu(+bias)
// ---------------------------------------------------------------------------
#define TSTR 36
#define TILE_FLOATS (128 * TSTR)
#define GEMM_SMEM_BYTES (4 * TILE_FLOATS * 2 * (int)sizeof(float))  // 73728

__device__ __forceinline__ void ldg_tile(
    const float* __restrict__ A, const float* __restrict__ Bt,
    int bm, int bn, int K, int k0, int tid, float4* ar, float4* br)
{
    const int row = tid >> 3;
    const int col = (tid & 7) * 4;
#pragma unroll
    for (int it = 0; it < 4; it++) {
        ar[it] = *(const float4*)(A  + (size_t)(bm + row + it * 32) * K + k0 + col);
        br[it] = *(const float4*)(Bt + (size_t)(bn + row + it * 32) * K + k0 + col);
    }
}

__device__ __forceinline__ void sts_tile(
    float* sA, float* sB, int tid, const float4* ar, const float4* br)
{
    const int row = tid >> 3;
    const int col = (tid & 7) * 4;
#pragma unroll
    for (int it = 0; it < 4; it++) {
        float4 v = ar[it];
        v.x = cvt_tf32(v.x); v.y = cvt_tf32(v.y);
        v.z = cvt_tf32(v.z); v.w = cvt_tf32(v.w);
        *(float4*)(sA + (row + it * 32) * TSTR + col) = v;
        float4 w = br[it];
        w.x = cvt_tf32(w.x); w.y = cvt_tf32(w.y);
        w.z = cvt_tf32(w.z); w.w = cvt_tf32(w.w);
        *(float4*)(sB + (row + it * 32) * TSTR + col) = w;
    }
}

template <int EPI>
__global__ void __launch_bounds__(256) gemm_mma_kernel(
    const float* __restrict__ A, const float* __restrict__ Bt,
    const float* __restrict__ bias, const float* __restrict__ res,
    float* __restrict__ C, int M, int N, int K)
{
    extern __shared__ float smf[];
    float* sA[2] = { smf,                   smf + 2 * TILE_FLOATS };
    float* sB[2] = { smf + TILE_FLOATS,     smf + 3 * TILE_FLOATS };

    const int tid  = threadIdx.x;
    const int lane = tid & 31;
    const int w    = tid >> 5;
    const int wm   = w >> 2;       // 0..1
    const int wn   = w & 3;        // 0..3
    const int bm   = blockIdx.y * 128;
    const int bn   = blockIdx.x * 128;
    const int nk   = K >> 5;

    float acc[4][4][4];
#pragma unroll
    for (int i = 0; i < 4; i++)
#pragma unroll
        for (int j = 0; j < 4; j++)
#pragma unroll
            for (int r = 0; r < 4; r++) acc[i][j][r] = 0.f;

    {
        float4 ar[4], br[4];
        ldg_tile(A, Bt, bm, bn, K, 0, tid, ar, br);
        sts_tile(sA[0], sB[0], tid, ar, br);
    }
    __syncthreads();

    for (int kt = 0; kt < nk; kt++) {
        const int cur = kt & 1;
        float4 ar[4], br[4];
        if (kt + 1 < nk)
            ldg_tile(A, Bt, bm, bn, K, (kt + 1) << 5, tid, ar, br);

        const float* cA = sA[cur];
        const float* cB = sB[cur];
#pragma unroll
        for (int kk = 0; kk < 4; kk++) {
            const int kb = kk * 8;
            uint32_t af[4][4], bf[4][2];
#pragma unroll
            for (int i = 0; i < 4; i++) {
                const float* p = cA + (wm * 64 + i * 16 + (lane >> 2)) * TSTR + kb + (lane & 3);
                af[i][0] = __float_as_uint(p[0]);
                af[i][1] = __float_as_uint(p[8 * TSTR]);
                af[i][2] = __float_as_uint(p[4]);
                af[i][3] = __float_as_uint(p[8 * TSTR + 4]);
            }
#pragma unroll
            for (int j = 0; j < 4; j++) {
                const float* p = cB + (wn * 32 + j * 8 + (lane >> 2)) * TSTR + kb + (lane & 3);
                bf[j][0] = __float_as_uint(p[0]);
                bf[j][1] = __float_as_uint(p[4]);
            }
#pragma unroll
            for (int i = 0; i < 4; i++)
#pragma unroll
                for (int j = 0; j < 4; j++)
                    mma_tf32(acc[i][j], af[i], bf[j]);
        }

        if (kt + 1 < nk)
            sts_tile(sA[cur ^ 1], sB[cur ^ 1], tid, ar, br);
        __syncthreads();
    }

    // epilogue: each thread owns (row, col..col+1) and (row+8, col..col+1) per frag
#pragma unroll
    for (int i = 0; i < 4; i++) {
#pragma unroll
        for (int j = 0; j < 4; j++) {
            const int row = bm + wm * 64 + i * 16 + (lane >> 2);
            const int col = bn + wn * 32 + j * 8 + (lane & 3) * 2;
            const float2 bv = *(const float2*)(bias + col);
#pragma unroll
            for (int half = 0; half < 2; half++) {
                const int r = row + half * 8;
                float2 v;
                v.x = acc[i][j][half * 2 + 0] + bv.x;
                v.y = acc[i][j][half * 2 + 1] + bv.y;
                if (EPI == 1) {
                    float2 rv = *(const float2*)(res + (size_t)r * N + col);
                    v.x += rv.x; v.y += rv.y;
                }
                if (EPI == 2) {
                    v.x = fmaxf(v.x, 0.f); v.y = fmaxf(v.y, 0.f);
                }
                *(float2*)(C + (size_t)r * N + col) = v;
            }
        }
    }
}

// ---------------------------------------------------------------------------
// Transpose: in [K, N] row-major -> out [N, K] row-major. block (32, 8).
// ---------------------------------------------------------------------------
__global__ void __launch_bounds__(256) transpose_kernel(
    const float* __restrict__ in, float* __restrict__ out,
    int K, int N, long inz, long outz)
{
    __shared__ float t[32][33];
    in  += (size_t)blockIdx.z * inz;
    out += (size_t)blockIdx.z * outz;
    const int k0 = blockIdx.y * 32;
    const int n0 = blockIdx.x * 32;
#pragma unroll
    for (int i = 0; i < 32; i += 8)
        t[threadIdx.y + i][threadIdx.x] =
            in[(size_t)(k0 + threadIdx.y + i) * N + n0 + threadIdx.x];
    __syncthreads();
#pragma unroll
    for (int i = 0; i < 32; i += 8)
        out[(size_t)(n0 + threadIdx.y + i) * K + k0 + threadIdx.x] =
            t[threadIdx.x][threadIdx.y + i];
}

// ---------------------------------------------------------------------------
// Flash attention, fp32 (proven round-1 version)
// ---------------------------------------------------------------------------
#define FA_SMEM_FLOATS (3 * 64 * 132 + 64 * 68 + 3 * 64)

__global__ void __launch_bounds__(256) flash_attn_kernel(
    const float* __restrict__ qb, const float* __restrict__ kb,
    const float* __restrict__ vb, float* __restrict__ heads)
{
    extern __shared__ float sm[];
    float* Qs = sm;
    float* Ks = Qs + 64 * 132;
    float* Vs = Ks + 64 * 132;
    float* Ss = Vs + 64 * 132;
    float* m_s  = Ss + 64 * 68;
    float* l_s  = m_s + 64;
    float* al_s = l_s + 64;

    const int h   = blockIdx.y;
    const int q0  = blockIdx.x * 64;
    const int tid = threadIdx.x;
    const float scale = 0.08838834764831845f;

    {
        int idx = tid * 4;
#pragma unroll
        for (int it = 0; it < 8; ++it) {
            int r = idx >> 7, c = idx & 127;
            *(float4*)(Qs + r * 132 + c) =
                *(const float4*)(qb + (size_t)(q0 + r) * D_DIM + h * 128 + c);
            idx += 1024;
        }
    }
    if (tid < 64) { m_s[tid] = -1e30f; l_s[tid] = 0.f; al_s[tid] = 0.f; }

    float O[8][4];
#pragma unroll
    for (int i = 0; i < 8; i++)
#pragma unroll
        for (int c = 0; c < 4; c++) O[i][c] = 0.f;

    const int oty = tid >> 5;
    const int otx = tid & 31;
    const int sty = tid >> 4;
    const int stx = tid & 15;
    const int srow = tid >> 2;
    const int sq   = tid & 3;

    for (int kblk = 0; kblk < 64; ++kblk) {
        __syncthreads();
        {
            int idx = tid * 4;
#pragma unroll
            for (int it = 0; it < 8; ++it) {
                int r = idx >> 7, c = idx & 127;
                size_t g = (size_t)(kblk * 64 + r) * D_DIM + h * 128 + c;
                *(float4*)(Ks + r * 132 + c) = *(const float4*)(kb + g);
                *(float4*)(Vs + r * 132 + c) = *(const float4*)(vb + g);
                idx += 1024;
            }
        }
        __syncthreads();

        {
            float acc[4][4];
#pragma unroll
            for (int i = 0; i < 4; i++)
#pragma unroll
                for (int j = 0; j < 4; j++) acc[i][j] = 0.f;
#pragma unroll 4
            for (int e = 0; e < 128; ++e) {
                float qv[4], kv[4];
#pragma unroll
                for (int i = 0; i < 4; i++) qv[i] = Qs[(sty * 4 + i) * 132 + e];
#pragma unroll
                for (int j = 0; j < 4; j++) kv[j] = Ks[(stx * 4 + j) * 132 + e];
#pragma unroll
                for (int i = 0; i < 4; i++)
#pragma unroll
                    for (int j = 0; j < 4; j++) acc[i][j] += qv[i] * kv[j];
            }
#pragma unroll
            for (int i = 0; i < 4; i++)
#pragma unroll
                for (int j = 0; j < 4; j++)
                    Ss[(sty * 4 + i) * 68 + stx * 4 + j] = acc[i][j] * scale;
        }
        __syncthreads();

        {
            float sv[16];
            float mx = -1e30f;
#pragma unroll
            for (int c = 0; c < 16; c++) {
                sv[c] = Ss[srow * 68 + sq * 16 + c];
                mx = fmaxf(mx, sv[c]);
            }
            mx = fmaxf(mx, __shfl_xor_sync(0xffffffffu, mx, 1));
            mx = fmaxf(mx, __shfl_xor_sync(0xffffffffu, mx, 2));
            const float m_old = m_s[srow];
            const float m_new = fmaxf(m_old, mx);
            float lsum = 0.f;
#pragma unroll
            for (int c = 0; c < 16; c++) {
                float p = __expf(sv[c] - m_new);
                Ss[srow * 68 + sq * 16 + c] = p;
                lsum += p;
            }
            lsum += __shfl_xor_sync(0xffffffffu, lsum, 1);
            lsum += __shfl_xor_sync(0xffffffffu, lsum, 2);
            if (sq == 0) {
                float alpha = __expf(m_old - m_new);
                l_s[srow] = l_s[srow] * alpha + lsum;
                m_s[srow] = m_new;
                al_s[srow] = alpha;
            }
        }
        __syncthreads();

#pragma unroll
        for (int i = 0; i < 8; i++) {
            const float alpha = al_s[oty * 8 + i];
#pragma unroll
            for (int c = 0; c < 4; c++) O[i][c] *= alpha;
        }
        for (int j = 0; j < 64; ++j) {
            float vv[4];
#pragma unroll
            for (int c = 0; c < 4; c++) vv[c] = Vs[j * 132 + otx + 32 * c];
#pragma unroll
            for (int i = 0; i < 8; i++) {
                const float p = Ss[(oty * 8 + i) * 68 + j];
#pragma unroll
                for (int c = 0; c < 4; c++) O[i][c] += p * vv[c];
            }
        }
    }
    __syncthreads();

#pragma unroll
    for (int i = 0; i < 8; i++) {
        const int r = oty * 8 + i;
        const float inv = 1.f / l_s[r];
#pragma unroll
        for (int c = 0; c < 4; c++) {
            heads[(size_t)(q0 + r) * D_DIM + h * 128 + otx + 32 * c] = O[i][c] * inv;
        }
    }
}

// ---------------------------------------------------------------------------
// LayerNorm
// ---------------------------------------------------------------------------
__global__ void __launch_bounds__(256) layernorm_kernel(
    const float* __restrict__ in, const float* __restrict__ gamma,
    const float* __restrict__ beta, float* __restrict__ out)
{
    __shared__ float red[16];
    const int row = blockIdx.x;
    const int tid = threadIdx.x;
    const float* rp = in + (size_t)row * D_DIM;

    float v[8];
    float s = 0.f, sq = 0.f;
#pragma unroll
    for (int it = 0; it < 2; ++it) {
        float4 t = *(const float4*)(rp + tid * 4 + it * 1024);
        v[it * 4 + 0] = t.x; v[it * 4 + 1] = t.y;
        v[it * 4 + 2] = t.z; v[it * 4 + 3] = t.w;
    }
#pragma unroll
    for (int i = 0; i < 8; i++) { s += v[i]; sq += v[i] * v[i]; }
#pragma unroll
    for (int o = 16; o > 0; o >>= 1) {
        s  += __shfl_xor_sync(0xffffffffu, s, o);
        sq += __shfl_xor_sync(0xffffffffu, sq, o);
    }
    if ((tid & 31) == 0) { red[tid >> 5] = s; red[8 + (tid >> 5)] = sq; }
    __syncthreads();
    if (tid < 32) {
        float ss = (tid < 8) ? red[tid] : 0.f;
        float qq = (tid < 8) ? red[8 + tid] : 0.f;
#pragma unroll
        for (int o = 4; o > 0; o >>= 1) {
            ss += __shfl_xor_sync(0xffffffffu, ss, o);
            qq += __shfl_xor_sync(0xffffffffu, qq, o);
        }
        if (tid == 0) { red[0] = ss; red[1] = qq; }
    }
    __syncthreads();
    const float mu  = red[0] * (1.f / D_DIM);
    const float var = red[1] * (1.f / D_DIM) - mu * mu;
    const float rs  = rsqrtf(var + 1e-5f);
#pragma unroll
    for (int it = 0; it < 2; ++it) {
        const int c = tid * 4 + it * 1024;
        float4 g = *(const float4*)(gamma + c);
        float4 b = *(const float4*)(beta + c);
        float4 o;
        o.x = (v[it * 4 + 0] - mu) * rs * g.x + b.x;
        o.y = (v[it * 4 + 1] - mu) * rs * g.y + b.y;
        o.z = (v[it * 4 + 2] - mu) * rs * g.z + b.z;
        o.w = (v[it * 4 + 3] - mu) * rs * g.w + b.w;
        *(float4*)(out + (size_t)row * D_DIM + c) = o;
    }
}

// ---------------------------------------------------------------------------
// Launch
// ---------------------------------------------------------------------------
extern "C" void kernel_launch(void* const* d_in, const int* in_sizes, int n_in,
                              void* d_out, int out_size)
{
    const float* x     = (const float*)d_in[0];
    const float* Wq    = (const float*)d_in[1];
    const float* bq    = (const float*)d_in[2];
    const float* Wk    = (const float*)d_in[3];
    const float* bk    = (const float*)d_in[4];
    const float* Wv    = (const float*)d_in[5];
    const float* bv    = (const float*)d_in[6];
    const float* Wp    = (const float*)d_in[7];
    const float* bp    = (const float*)d_in[8];
    const float* W1    = (const float*)d_in[9];
    const float* b1    = (const float*)d_in[10];
    const float* W2    = (const float*)d_in[11];
    const float* b2    = (const float*)d_in[12];
    const float* gamma = (const float*)d_in[13];
    const float* beta  = (const float*)d_in[14];
    float* out = (float*)d_out;

    float *q, *k, *v, *heads, *proj, *ln, *h1;
    float *wqt, *wkt, *wvt, *wpt, *w1t, *w2t;
    cudaGetSymbolAddress((void**)&q,     g_q);
    cudaGetSymbolAddress((void**)&k,     g_k);
    cudaGetSymbolAddress((void**)&v,     g_v);
    cudaGetSymbolAddress((void**)&heads, g_heads);
    cudaGetSymbolAddress((void**)&proj,  g_proj);
    cudaGetSymbolAddress((void**)&ln,    g_ln);
    cudaGetSymbolAddress((void**)&h1,    g_h1);
    cudaGetSymbolAddress((void**)&wqt,   g_wqt);
    cudaGetSymbolAddress((void**)&wkt,   g_wkt);
    cudaGetSymbolAddress((void**)&wvt,   g_wvt);
    cudaGetSymbolAddress((void**)&wpt,   g_wpt);
    cudaGetSymbolAddress((void**)&w1t,   g_w1t);
    cudaGetSymbolAddress((void**)&w2t,   g_w2t);

    // ---- weight transposes to [N, K] ----
    const dim3 tb(32, 8);
    transpose_kernel<<<dim3(4, 64, 16), tb>>>(Wq, wqt, D_DIM, 128, (long)D_DIM * 128, (long)128 * D_DIM);
    transpose_kernel<<<dim3(4, 64, 16), tb>>>(Wk, wkt, D_DIM, 128, (long)D_DIM * 128, (long)128 * D_DIM);
    transpose_kernel<<<dim3(4, 64, 16), tb>>>(Wv, wvt, D_DIM, 128, (long)D_DIM * 128, (long)128 * D_DIM);
    transpose_kernel<<<dim3(64, 64, 1),  tb>>>(Wp, wpt, D_DIM, D_DIM, 0, 0);
    transpose_kernel<<<dim3(256, 64, 1), tb>>>(W1, w1t, D_DIM, F_DIM, 0, 0);
    transpose_kernel<<<dim3(64, 256, 1), tb>>>(W2, w2t, F_DIM, D_DIM, 0, 0);

    // ---- tf32 warp-MMA GEMMs ----
    cudaFuncSetAttribute(gemm_mma_kernel<0>, cudaFuncAttributeMaxDynamicSharedMemorySize, GEMM_SMEM_BYTES);
    cudaFuncSetAttribute(gemm_mma_kernel<1>, cudaFuncAttributeMaxDynamicSharedMemorySize, GEMM_SMEM_BYTES);
    cudaFuncSetAttribute(gemm_mma_kernel<2>, cudaFuncAttributeMaxDynamicSharedMemorySize, GEMM_SMEM_BYTES);

    const dim3 blk(256);
    const dim3 g_dd(D_DIM / 128, S_LEN / 128);   // (16, 32)
    const dim3 g_f1(F_DIM / 128, S_LEN / 128);   // (64, 32)

    gemm_mma_kernel<0><<<g_dd, blk, GEMM_SMEM_BYTES>>>(x, wqt, bq, nullptr, q, S_LEN, D_DIM, D_DIM);
    gemm_mma_kernel<0><<<g_dd, blk, GEMM_SMEM_BYTES>>>(x, wkt, bk, nullptr, k, S_LEN, D_DIM, D_DIM);
    gemm_mma_kernel<0><<<g_dd, blk, GEMM_SMEM_BYTES>>>(x, wvt, bv, nullptr, v, S_LEN, D_DIM, D_DIM);

    // ---- flash attention (fp32) ----
    const int fa_smem = FA_SMEM_FLOATS * (int)sizeof(float);
    cudaFuncSetAttribute(flash_attn_kernel, cudaFuncAttributeMaxDynamicSharedMemorySize, fa_smem);
    flash_attn_kernel<<<dim3(S_LEN / 64, H_NUM), blk, fa_smem>>>(q, k, v, heads);

    // ---- output projection + residual, LayerNorm ----
    gemm_mma_kernel<1><<<g_dd, blk, GEMM_SMEM_BYTES>>>(heads, wpt, bp, x, proj, S_LEN, D_DIM, D_DIM);
    layernorm_kernel<<<S_LEN, blk>>>(proj, gamma, beta, ln);

    // ---- FFN ----
    gemm_mma_kernel<2><<<g_f1, blk, GEMM_SMEM_BYTES>>>(ln, w1t, b1, nullptr, h1, S_LEN, F_DIM, D_DIM);
    gemm_mma_kernel<0><<<g_dd, blk, GEMM_SMEM_BYTES>>>(h1, w2t, b2, nullptr, out, S_LEN, D_DIM, F_DIM);
}

// round 4
// speedup vs baseline: 2.5286x; 1.7209x over previous
#include <cuda_runtime.h>
#include <cstdint>

// Problem dims
#define S_LEN 4096
#define D_DIM 2048
#define H_NUM 16
#define F_DIM 8192

// ---------------------------------------------------------------------------
// Scratch (allocation is banned; use device globals)
// ---------------------------------------------------------------------------
__device__ float g_q[S_LEN * D_DIM];
__device__ float g_k[S_LEN * D_DIM];
__device__ float g_v[S_LEN * D_DIM];
__device__ float g_heads[S_LEN * D_DIM];
__device__ float g_proj[S_LEN * D_DIM];
__device__ float g_ln[S_LEN * D_DIM];
__device__ float g_h1[S_LEN * F_DIM];
// transposed weights, [N, K] row-major
__device__ float g_wqt[D_DIM * D_DIM];
__device__ float g_wkt[D_DIM * D_DIM];
__device__ float g_wvt[D_DIM * D_DIM];
__device__ float g_wpt[D_DIM * D_DIM];
__device__ float g_w1t[F_DIM * D_DIM];
__device__ float g_w2t[D_DIM * F_DIM];

// ---------------------------------------------------------------------------
// tf32 helpers (sm_80+ portable; tcgen05 is gated off on plain sm_103 target)
// ---------------------------------------------------------------------------
__device__ __forceinline__ float cvt_tf32(float x) {
    float y;
    asm("cvt.rna.tf32.f32 %0, %1;" : "=f"(y) : "f"(x));
    return y;
}

__device__ __forceinline__ void mma_tf32(float* c, const uint32_t* a, const uint32_t* b) {
    asm volatile(
        "mma.sync.aligned.m16n8k8.row.col.f32.tf32.tf32.f32 "
        "{%0,%1,%2,%3}, {%4,%5,%6,%7}, {%8,%9}, {%0,%1,%2,%3};"
        : "+f"(c[0]), "+f"(c[1]), "+f"(c[2]), "+f"(c[3])
        : "r"(a[0]), "r"(a[1]), "r"(a[2]), "r"(a[3]), "r"(b[0]), "r"(b[1]));
}

// ---------------------------------------------------------------------------
// tf32 warp-MMA GEMM: C[M,N] = A[M,K] @ Bt[N,K]^T + epilogue (unchanged R3)
// ---------------------------------------------------------------------------
#define TSTR 36
#define TILE_FLOATS (128 * TSTR)
#define GEMM_SMEM_BYTES (4 * TILE_FLOATS * 2 * (int)sizeof(float))  // 73728

__device__ __forceinline__ void ldg_tile(
    const float* __restrict__ A, const float* __restrict__ Bt,
    int bm, int bn, int K, int k0, int tid, float4* ar, float4* br)
{
    const int row = tid >> 3;
    const int col = (tid & 7) * 4;
#pragma unroll
    for (int it = 0; it < 4; it++) {
        ar[it] = *(const float4*)(A  + (size_t)(bm + row + it * 32) * K + k0 + col);
        br[it] = *(const float4*)(Bt + (size_t)(bn + row + it * 32) * K + k0 + col);
    }
}

__device__ __forceinline__ void sts_tile(
    float* sA, float* sB, int tid, const float4* ar, const float4* br)
{
    const int row = tid >> 3;
    const int col = (tid & 7) * 4;
#pragma unroll
    for (int it = 0; it < 4; it++) {
        float4 v = ar[it];
        v.x = cvt_tf32(v.x); v.y = cvt_tf32(v.y);
        v.z = cvt_tf32(v.z); v.w = cvt_tf32(v.w);
        *(float4*)(sA + (row + it * 32) * TSTR + col) = v;
        float4 w = br[it];
        w.x = cvt_tf32(w.x); w.y = cvt_tf32(w.y);
        w.z = cvt_tf32(w.z); w.w = cvt_tf32(w.w);
        *(float4*)(sB + (row + it * 32) * TSTR + col) = w;
    }
}

template <int EPI>
__global__ void __launch_bounds__(256) gemm_mma_kernel(
    const float* __restrict__ A, const float* __restrict__ Bt,
    const float* __restrict__ bias, const float* __restrict__ res,
    float* __restrict__ C, int M, int N, int K)
{
    extern __shared__ float smf[];
    float* sA[2] = { smf,                   smf + 2 * TILE_FLOATS };
    float* sB[2] = { smf + TILE_FLOATS,     smf + 3 * TILE_FLOATS };

    const int tid  = threadIdx.x;
    const int lane = tid & 31;
    const int w    = tid >> 5;
    const int wm   = w >> 2;
    const int wn   = w & 3;
    const int bm   = blockIdx.y * 128;
    const int bn   = blockIdx.x * 128;
    const int nk   = K >> 5;

    float acc[4][4][4];
#pragma unroll
    for (int i = 0; i < 4; i++)
#pragma unroll
        for (int j = 0; j < 4; j++)
#pragma unroll
            for (int r = 0; r < 4; r++) acc[i][j][r] = 0.f;

    {
        float4 ar[4], br[4];
        ldg_tile(A, Bt, bm, bn, K, 0, tid, ar, br);
        sts_tile(sA[0], sB[0], tid, ar, br);
    }
    __syncthreads();

    for (int kt = 0; kt < nk; kt++) {
        const int cur = kt & 1;
        float4 ar[4], br[4];
        if (kt + 1 < nk)
            ldg_tile(A, Bt, bm, bn, K, (kt + 1) << 5, tid, ar, br);

        const float* cA = sA[cur];
        const float* cB = sB[cur];
#pragma unroll
        for (int kk = 0; kk < 4; kk++) {
            const int kb = kk * 8;
            uint32_t af[4][4], bf[4][2];
#pragma unroll
            for (int i = 0; i < 4; i++) {
                const float* p = cA + (wm * 64 + i * 16 + (lane >> 2)) * TSTR + kb + (lane & 3);
                af[i][0] = __float_as_uint(p[0]);
                af[i][1] = __float_as_uint(p[8 * TSTR]);
                af[i][2] = __float_as_uint(p[4]);
                af[i][3] = __float_as_uint(p[8 * TSTR + 4]);
            }
#pragma unroll
            for (int j = 0; j < 4; j++) {
                const float* p = cB + (wn * 32 + j * 8 + (lane >> 2)) * TSTR + kb + (lane & 3);
                bf[j][0] = __float_as_uint(p[0]);
                bf[j][1] = __float_as_uint(p[4]);
            }
#pragma unroll
            for (int i = 0; i < 4; i++)
#pragma unroll
                for (int j = 0; j < 4; j++)
                    mma_tf32(acc[i][j], af[i], bf[j]);
        }

        if (kt + 1 < nk)
            sts_tile(sA[cur ^ 1], sB[cur ^ 1], tid, ar, br);
        __syncthreads();
    }

#pragma unroll
    for (int i = 0; i < 4; i++) {
#pragma unroll
        for (int j = 0; j < 4; j++) {
            const int row = bm + wm * 64 + i * 16 + (lane >> 2);
            const int col = bn + wn * 32 + j * 8 + (lane & 3) * 2;
            const float2 bv = *(const float2*)(bias + col);
#pragma unroll
            for (int half = 0; half < 2; half++) {
                const int r = row + half * 8;
                float2 v;
                v.x = acc[i][j][half * 2 + 0] + bv.x;
                v.y = acc[i][j][half * 2 + 1] + bv.y;
                if (EPI == 1) {
                    float2 rv = *(const float2*)(res + (size_t)r * N + col);
                    v.x += rv.x; v.y += rv.y;
                }
                if (EPI == 2) {
                    v.x = fmaxf(v.x, 0.f); v.y = fmaxf(v.y, 0.f);
                }
                *(float2*)(C + (size_t)r * N + col) = v;
            }
        }
    }
}

// ---------------------------------------------------------------------------
// Transpose: in [K, N] row-major -> out [N, K] row-major. block (32, 8).
// ---------------------------------------------------------------------------
__global__ void __launch_bounds__(256) transpose_kernel(
    const float* __restrict__ in, float* __restrict__ out,
    int K, int N, long inz, long outz)
{
    __shared__ float t[32][33];
    in  += (size_t)blockIdx.z * inz;
    out += (size_t)blockIdx.z * outz;
    const int k0 = blockIdx.y * 32;
    const int n0 = blockIdx.x * 32;
#pragma unroll
    for (int i = 0; i < 32; i += 8)
        t[threadIdx.y + i][threadIdx.x] =
            in[(size_t)(k0 + threadIdx.y + i) * N + n0 + threadIdx.x];
    __syncthreads();
#pragma unroll
    for (int i = 0; i < 32; i += 8)
        out[(size_t)(n0 + threadIdx.y + i) * K + k0 + threadIdx.x] =
            t[threadIdx.x][threadIdx.y + i];
}

// ---------------------------------------------------------------------------
// Flash attention with tf32 mma.sync.
// Q tile 64 rows x one head; K tile 64. 256 threads = 8 warps (4m x 2n).
// QK^T: warp tile 16x32. PV: warp tile 16x64 (O in registers).
// Strides: Q/K = 132 (conflict-free a/b frags), V = 136 (conflict-free b),
// S = 68 (conflict-free P a-frags).
// ---------------------------------------------------------------------------
#define QKSTR 132
#define VSTR 136
#define SSTR 68
#define FA_SMEM_FLOATS (2 * 64 * QKSTR + 64 * VSTR + 64 * SSTR + 3 * 64)

__global__ void __launch_bounds__(256) flash_attn_tf32_kernel(
    const float* __restrict__ qb, const float* __restrict__ kb,
    const float* __restrict__ vb, float* __restrict__ heads)
{
    extern __shared__ float sm[];
    float* Qs = sm;                         // 64 x 132
    float* Ks = Qs + 64 * QKSTR;            // 64 x 132
    float* Vs = Ks + 64 * QKSTR;            // 64 x 136
    float* Ss = Vs + 64 * VSTR;             // 64 x 68
    float* m_s  = Ss + 64 * SSTR;
    float* l_s  = m_s + 64;
    float* al_s = l_s + 64;

    const int h    = blockIdx.y;
    const int q0   = blockIdx.x * 64;
    const int tid  = threadIdx.x;
    const int lane = tid & 31;
    const int w    = tid >> 5;
    const int wm   = w >> 1;      // 0..3 -> rows wm*16
    const int wn   = w & 1;       // 0..1
    const float scale = 0.08838834764831845f;  // 1/sqrt(128)

    const int r0 = wm * 16 + (lane >> 2);   // fragment row (and +8)
    const int kq = lane & 3;

    // load Q tile (tf32-rounded)
    {
        int idx = tid * 4;
#pragma unroll
        for (int it = 0; it < 8; ++it) {
            int r = idx >> 7, c = idx & 127;
            float4 v = *(const float4*)(qb + (size_t)(q0 + r) * D_DIM + h * 128 + c);
            v.x = cvt_tf32(v.x); v.y = cvt_tf32(v.y);
            v.z = cvt_tf32(v.z); v.w = cvt_tf32(v.w);
            *(float4*)(Qs + r * QKSTR + c) = v;
            idx += 1024;
        }
    }
    if (tid < 64) { m_s[tid] = -1e30f; l_s[tid] = 0.f; al_s[tid] = 0.f; }

    float O[8][4];
#pragma unroll
    for (int j = 0; j < 8; j++)
#pragma unroll
        for (int r = 0; r < 4; r++) O[j][r] = 0.f;

    const int srow = tid >> 2;
    const int sq   = tid & 3;

    for (int kblk = 0; kblk < 64; ++kblk) {
        __syncthreads();  // Ks/Vs/Ss free
        {
            int idx = tid * 4;
#pragma unroll
            for (int it = 0; it < 8; ++it) {
                int r = idx >> 7, c = idx & 127;
                size_t g = (size_t)(kblk * 64 + r) * D_DIM + h * 128 + c;
                float4 kv = *(const float4*)(kb + g);
                kv.x = cvt_tf32(kv.x); kv.y = cvt_tf32(kv.y);
                kv.z = cvt_tf32(kv.z); kv.w = cvt_tf32(kv.w);
                *(float4*)(Ks + r * QKSTR + c) = kv;
                float4 vv = *(const float4*)(vb + g);
                vv.x = cvt_tf32(vv.x); vv.y = cvt_tf32(vv.y);
                vv.z = cvt_tf32(vv.z); vv.w = cvt_tf32(vv.w);
                *(float4*)(Vs + r * VSTR + c) = vv;
                idx += 1024;
            }
        }
        __syncthreads();

        // S = scale * Q @ K^T  via mma (warp tile 16x32)
        {
            float sacc[4][4];
#pragma unroll
            for (int j = 0; j < 4; j++)
#pragma unroll
                for (int r = 0; r < 4; r++) sacc[j][r] = 0.f;
#pragma unroll
            for (int kb8 = 0; kb8 < 16; ++kb8) {
                const int kk = kb8 * 8 + kq;
                uint32_t af[4];
                const float* ap = Qs + r0 * QKSTR + kk;
                af[0] = __float_as_uint(ap[0]);
                af[1] = __float_as_uint(ap[8 * QKSTR]);
                af[2] = __float_as_uint(ap[4]);
                af[3] = __float_as_uint(ap[8 * QKSTR + 4]);
#pragma unroll
                for (int j = 0; j < 4; j++) {
                    const float* bp = Ks + (wn * 32 + j * 8 + (lane >> 2)) * QKSTR + kk;
                    uint32_t bf[2];
                    bf[0] = __float_as_uint(bp[0]);
                    bf[1] = __float_as_uint(bp[4]);
                    mma_tf32(sacc[j], af, bf);
                }
            }
#pragma unroll
            for (int j = 0; j < 4; j++) {
                const int col = wn * 32 + j * 8 + (lane & 3) * 2;
                float2 v0 = { sacc[j][0] * scale, sacc[j][1] * scale };
                float2 v1 = { sacc[j][2] * scale, sacc[j][3] * scale };
                *(float2*)(Ss + r0 * SSTR + col) = v0;
                *(float2*)(Ss + (r0 + 8) * SSTR + col) = v1;
            }
        }
        __syncthreads();

        // online softmax per row (4 threads per row); store tf32-rounded P
        {
            float sv[16];
            float mx = -1e30f;
#pragma unroll
            for (int c = 0; c < 16; c++) {
                sv[c] = Ss[srow * SSTR + sq * 16 + c];
                mx = fmaxf(mx, sv[c]);
            }
            mx = fmaxf(mx, __shfl_xor_sync(0xffffffffu, mx, 1));
            mx = fmaxf(mx, __shfl_xor_sync(0xffffffffu, mx, 2));
            const float m_old = m_s[srow];
            const float m_new = fmaxf(m_old, mx);
            float lsum = 0.f;
#pragma unroll
            for (int c = 0; c < 16; c++) {
                float p = cvt_tf32(__expf(sv[c] - m_new));
                Ss[srow * SSTR + sq * 16 + c] = p;
                lsum += p;
            }
            lsum += __shfl_xor_sync(0xffffffffu, lsum, 1);
            lsum += __shfl_xor_sync(0xffffffffu, lsum, 2);
            if (sq == 0) {
                float alpha = __expf(m_old - m_new);
                l_s[srow] = l_s[srow] * alpha + lsum;
                m_s[srow] = m_new;
                al_s[srow] = alpha;
            }
        }
        __syncthreads();

        // O = O*alpha + P @ V  via mma (warp tile 16x64)
        {
            const float al0 = al_s[r0];
            const float al1 = al_s[r0 + 8];
#pragma unroll
            for (int j = 0; j < 8; j++) {
                O[j][0] *= al0; O[j][1] *= al0;
                O[j][2] *= al1; O[j][3] *= al1;
            }
#pragma unroll
            for (int kb8 = 0; kb8 < 8; ++kb8) {
                const int kk = kb8 * 8 + kq;
                uint32_t af[4];
                const float* ap = Ss + r0 * SSTR + kk;
                af[0] = __float_as_uint(ap[0]);
                af[1] = __float_as_uint(ap[8 * SSTR]);
                af[2] = __float_as_uint(ap[4]);
                af[3] = __float_as_uint(ap[8 * SSTR + 4]);
#pragma unroll
                for (int j = 0; j < 8; j++) {
                    const float* bp = Vs + kk * VSTR + wn * 64 + j * 8 + (lane >> 2);
                    uint32_t bf[2];
                    bf[0] = __float_as_uint(bp[0]);
                    bf[1] = __float_as_uint(bp[4 * VSTR]);
                    mma_tf32(O[j], af, bf);
                }
            }
        }
    }
    __syncthreads();

    // normalize + write heads
    {
        const float il0 = 1.f / l_s[r0];
        const float il1 = 1.f / l_s[r0 + 8];
#pragma unroll
        for (int j = 0; j < 8; j++) {
            const int col = h * 128 + wn * 64 + j * 8 + (lane & 3) * 2;
            float2 v0 = { O[j][0] * il0, O[j][1] * il0 };
            float2 v1 = { O[j][2] * il1, O[j][3] * il1 };
            *(float2*)(heads + (size_t)(q0 + r0) * D_DIM + col) = v0;
            *(float2*)(heads + (size_t)(q0 + r0 + 8) * D_DIM + col) = v1;
        }
    }
}

// ---------------------------------------------------------------------------
// LayerNorm (unchanged)
// ---------------------------------------------------------------------------
__global__ void __launch_bounds__(256) layernorm_kernel(
    const float* __restrict__ in, const float* __restrict__ gamma,
    const float* __restrict__ beta, float* __restrict__ out)
{
    __shared__ float red[16];
    const int row = blockIdx.x;
    const int tid = threadIdx.x;
    const float* rp = in + (size_t)row * D_DIM;

    float v[8];
    float s = 0.f, sq = 0.f;
#pragma unroll
    for (int it = 0; it < 2; ++it) {
        float4 t = *(const float4*)(rp + tid * 4 + it * 1024);
        v[it * 4 + 0] = t.x; v[it * 4 + 1] = t.y;
        v[it * 4 + 2] = t.z; v[it * 4 + 3] = t.w;
    }
#pragma unroll
    for (int i = 0; i < 8; i++) { s += v[i]; sq += v[i] * v[i]; }
#pragma unroll
    for (int o = 16; o > 0; o >>= 1) {
        s  += __shfl_xor_sync(0xffffffffu, s, o);
        sq += __shfl_xor_sync(0xffffffffu, sq, o);
    }
    if ((tid & 31) == 0) { red[tid >> 5] = s; red[8 + (tid >> 5)] = sq; }
    __syncthreads();
    if (tid < 32) {
        float ss = (tid < 8) ? red[tid] : 0.f;
        float qq = (tid < 8) ? red[8 + tid] : 0.f;
#pragma unroll
        for (int o = 4; o > 0; o >>= 1) {
            ss += __shfl_xor_sync(0xffffffffu, ss, o);
            qq += __shfl_xor_sync(0xffffffffu, qq, o);
        }
        if (tid == 0) { red[0] = ss; red[1] = qq; }
    }
    __syncthreads();
    const float mu  = red[0] * (1.f / D_DIM);
    const float var = red[1] * (1.f / D_DIM) - mu * mu;
    const float rs  = rsqrtf(var + 1e-5f);
#pragma unroll
    for (int it = 0; it < 2; ++it) {
        const int c = tid * 4 + it * 1024;
        float4 g = *(const float4*)(gamma + c);
        float4 b = *(const float4*)(beta + c);
        float4 o;
        o.x = (v[it * 4 + 0] - mu) * rs * g.x + b.x;
        o.y = (v[it * 4 + 1] - mu) * rs * g.y + b.y;
        o.z = (v[it * 4 + 2] - mu) * rs * g.z + b.z;
        o.w = (v[it * 4 + 3] - mu) * rs * g.w + b.w;
        *(float4*)(out + (size_t)row * D_DIM + c) = o;
    }
}

// ---------------------------------------------------------------------------
// Launch
// ---------------------------------------------------------------------------
extern "C" void kernel_launch(void* const* d_in, const int* in_sizes, int n_in,
                              void* d_out, int out_size)
{
    const float* x     = (const float*)d_in[0];
    const float* Wq    = (const float*)d_in[1];
    const float* bq    = (const float*)d_in[2];
    const float* Wk    = (const float*)d_in[3];
    const float* bk    = (const float*)d_in[4];
    const float* Wv    = (const float*)d_in[5];
    const float* bv    = (const float*)d_in[6];
    const float* Wp    = (const float*)d_in[7];
    const float* bp    = (const float*)d_in[8];
    const float* W1    = (const float*)d_in[9];
    const float* b1    = (const float*)d_in[10];
    const float* W2    = (const float*)d_in[11];
    const float* b2    = (const float*)d_in[12];
    const float* gamma = (const float*)d_in[13];
    const float* beta  = (const float*)d_in[14];
    float* out = (float*)d_out;

    float *q, *k, *v, *heads, *proj, *ln, *h1;
    float *wqt, *wkt, *wvt, *wpt, *w1t, *w2t;
    cudaGetSymbolAddress((void**)&q,     g_q);
    cudaGetSymbolAddress((void**)&k,     g_k);
    cudaGetSymbolAddress((void**)&v,     g_v);
    cudaGetSymbolAddress((void**)&heads, g_heads);
    cudaGetSymbolAddress((void**)&proj,  g_proj);
    cudaGetSymbolAddress((void**)&ln,    g_ln);
    cudaGetSymbolAddress((void**)&h1,    g_h1);
    cudaGetSymbolAddress((void**)&wqt,   g_wqt);
    cudaGetSymbolAddress((void**)&wkt,   g_wkt);
    cudaGetSymbolAddress((void**)&wvt,   g_wvt);
    cudaGetSymbolAddress((void**)&wpt,   g_wpt);
    cudaGetSymbolAddress((void**)&w1t,   g_w1t);
    cudaGetSymbolAddress((void**)&w2t,   g_w2t);

    // ---- weight transposes to [N, K] ----
    const dim3 tb(32, 8);
    transpose_kernel<<<dim3(4, 64, 16), tb>>>(Wq, wqt, D_DIM, 128, (long)D_DIM * 128, (long)128 * D_DIM);
    transpose_kernel<<<dim3(4, 64, 16), tb>>>(Wk, wkt, D_DIM, 128, (long)D_DIM * 128, (long)128 * D_DIM);
    transpose_kernel<<<dim3(4, 64, 16), tb>>>(Wv, wvt, D_DIM, 128, (long)D_DIM * 128, (long)128 * D_DIM);
    transpose_kernel<<<dim3(64, 64, 1),  tb>>>(Wp, wpt, D_DIM, D_DIM, 0, 0);
    transpose_kernel<<<dim3(256, 64, 1), tb>>>(W1, w1t, D_DIM, F_DIM, 0, 0);
    transpose_kernel<<<dim3(64, 256, 1), tb>>>(W2, w2t, F_DIM, D_DIM, 0, 0);

    // ---- tf32 warp-MMA GEMMs ----
    cudaFuncSetAttribute(gemm_mma_kernel<0>, cudaFuncAttributeMaxDynamicSharedMemorySize, GEMM_SMEM_BYTES);
    cudaFuncSetAttribute(gemm_mma_kernel<1>, cudaFuncAttributeMaxDynamicSharedMemorySize, GEMM_SMEM_BYTES);
    cudaFuncSetAttribute(gemm_mma_kernel<2>, cudaFuncAttributeMaxDynamicSharedMemorySize, GEMM_SMEM_BYTES);

    const dim3 blk(256);
    const dim3 g_dd(D_DIM / 128, S_LEN / 128);   // (16, 32)
    const dim3 g_f1(F_DIM / 128, S_LEN / 128);   // (64, 32)

    gemm_mma_kernel<0><<<g_dd, blk, GEMM_SMEM_BYTES>>>(x, wqt, bq, nullptr, q, S_LEN, D_DIM, D_DIM);
    gemm_mma_kernel<0><<<g_dd, blk, GEMM_SMEM_BYTES>>>(x, wkt, bk, nullptr, k, S_LEN, D_DIM, D_DIM);
    gemm_mma_kernel<0><<<g_dd, blk, GEMM_SMEM_BYTES>>>(x, wvt, bv, nullptr, v, S_LEN, D_DIM, D_DIM);

    // ---- flash attention (tf32 mma) ----
    const int fa_smem = FA_SMEM_FLOATS * (int)sizeof(float);
    cudaFuncSetAttribute(flash_attn_tf32_kernel, cudaFuncAttributeMaxDynamicSharedMemorySize, fa_smem);
    flash_attn_tf32_kernel<<<dim3(S_LEN / 64, H_NUM), blk, fa_smem>>>(q, k, v, heads);

    // ---- output projection + residual, LayerNorm ----
    gemm_mma_kernel<1><<<g_dd, blk, GEMM_SMEM_BYTES>>>(heads, wpt, bp, x, proj, S_LEN, D_DIM, D_DIM);
    layernorm_kernel<<<S_LEN, blk>>>(proj, gamma, beta, ln);

    // ---- FFN ----
    gemm_mma_kernel<2><<<g_f1, blk, GEMM_SMEM_BYTES>>>(ln, w1t, b1, nullptr, h1, S_LEN, F_DIM, D_DIM);
    gemm_mma_kernel<0><<<g_dd, blk, GEMM_SMEM_BYTES>>>(h1, w2t, b2, nullptr, out, S_LEN, D_DIM, F_DIM);
}

// round 5
// speedup vs baseline: 5.1927x; 2.0536x over previous
#include <cuda_runtime.h>
#include <cuda_fp16.h>
#include <cstdint>

// Problem dims
#define S_LEN 4096
#define D_DIM 2048
#define H_NUM 16
#define F_DIM 8192

// ---------------------------------------------------------------------------
// Scratch (allocation is banned; use device globals)
// ---------------------------------------------------------------------------
__device__ __half g_qh[S_LEN * D_DIM];
__device__ __half g_kh[S_LEN * D_DIM];
__device__ __half g_vh[S_LEN * D_DIM];
__device__ __half g_headsh[S_LEN * D_DIM];
__device__ float  g_proj[S_LEN * D_DIM];
__device__ __half g_lnh[S_LEN * D_DIM];
__device__ __half g_h1h[S_LEN * F_DIM];
// transposed fp16 weights, [N, K] row-major
__device__ __half g_wqt[D_DIM * D_DIM];
__device__ __half g_wkt[D_DIM * D_DIM];
__device__ __half g_wvt[D_DIM * D_DIM];
__device__ __half g_wpt[D_DIM * D_DIM];
__device__ __half g_w1t[F_DIM * D_DIM];
__device__ __half g_w2t[D_DIM * F_DIM];

// ---------------------------------------------------------------------------
// fp16 mma helpers (sm_80+ portable; tcgen05 is gated off on plain sm_103)
// ---------------------------------------------------------------------------
__device__ __forceinline__ uint32_t packh2(float a, float b) {
    __half2 h = __floats2half2_rn(a, b);
    return *reinterpret_cast<uint32_t*>(&h);
}

__device__ __forceinline__ void mma_f16(float* c, const uint32_t* a,
                                        uint32_t b0, uint32_t b1) {
    asm volatile(
        "mma.sync.aligned.m16n8k16.row.col.f32.f16.f16.f32 "
        "{%0,%1,%2,%3}, {%4,%5,%6,%7}, {%8,%9}, {%0,%1,%2,%3};"
        : "+f"(c[0]), "+f"(c[1]), "+f"(c[2]), "+f"(c[3])
        : "r"(a[0]), "r"(a[1]), "r"(a[2]), "r"(a[3]), "r"(b0), "r"(b1));
}

// ---------------------------------------------------------------------------
// fp16 warp-MMA GEMM: C[M,N] = A[M,K] @ Bt[N,K]^T + epilogue
// CTA tile 128x128, BK=32 halves, 256 threads = 8 warps (2Mx4N), warp 64x32.
//   EPI 0: +bias   EPI 1: +bias+res   EPI 2: relu(+bias)
//   AH: A source is half (else fp32)   OH: output half (else fp32)
// smem stride 40 halves (20 words) -> conflict-free fragment LDS.
// ---------------------------------------------------------------------------
#define GSTR 40

template <int EPI, int AH, int OH>
__global__ void __launch_bounds__(256) gemm_h_kernel(
    const void* __restrict__ Av, const __half* __restrict__ Bt,
    const float* __restrict__ bias, const float* __restrict__ res,
    void* __restrict__ Cv, int M, int N, int K)
{
    __shared__ __half sh[20480];          // 40 KB: 2 x (A 128x40 + B 128x40)
    __half* sA[2] = { sh,        sh + 10240 };
    __half* sB[2] = { sh + 5120, sh + 15360 };

    const float*  Af = (const float*)Av;
    const __half* Ah = (const __half*)Av;
    float*  Cf = (float*)Cv;
    __half* Ch = (__half*)Cv;

    const int tid = threadIdx.x, lane = tid & 31, w = tid >> 5;
    const int wm = w >> 2, wn = w & 3;
    const int bm = blockIdx.y * 128, bn = blockIdx.x * 128;
    const int nk = K >> 5;
    const int lrow = tid >> 1;
    const int lcol = (tid & 1) * 16;

    float acc[4][4][4];
#pragma unroll
    for (int i = 0; i < 4; i++)
#pragma unroll
        for (int j = 0; j < 4; j++)
#pragma unroll
            for (int r = 0; r < 4; r++) acc[i][j][r] = 0.f;

    float4 arf[4];
    uint4  arh[2], brh[2];

    auto LDG = [&](int k0) {
        if (AH) {
            arh[0] = *(const uint4*)(Ah + (size_t)(bm + lrow) * K + k0 + lcol);
            arh[1] = *(const uint4*)(Ah + (size_t)(bm + lrow) * K + k0 + lcol + 8);
        } else {
#pragma unroll
            for (int it = 0; it < 4; it++)
                arf[it] = *(const float4*)(Af + (size_t)(bm + lrow) * K + k0 + lcol + it * 4);
        }
        brh[0] = *(const uint4*)(Bt + (size_t)(bn + lrow) * K + k0 + lcol);
        brh[1] = *(const uint4*)(Bt + (size_t)(bn + lrow) * K + k0 + lcol + 8);
    };
    auto STS = [&](int s) {
        if (AH) {
            *(uint4*)(sA[s] + lrow * GSTR + lcol) = arh[0];
            *(uint4*)(sA[s] + lrow * GSTR + lcol + 8) = arh[1];
        } else {
#pragma unroll
            for (int it = 0; it < 4; it++) {
                uint2 u;
                u.x = packh2(arf[it].x, arf[it].y);
                u.y = packh2(arf[it].z, arf[it].w);
                *(uint2*)(sA[s] + lrow * GSTR + lcol + it * 4) = u;
            }
        }
        *(uint4*)(sB[s] + lrow * GSTR + lcol) = brh[0];
        *(uint4*)(sB[s] + lrow * GSTR + lcol + 8) = brh[1];
    };

    LDG(0); STS(0);
    __syncthreads();

    for (int kt = 0; kt < nk; kt++) {
        const int cur = kt & 1;
        if (kt + 1 < nk) LDG((kt + 1) << 5);

        const uint32_t* cA = (const uint32_t*)sA[cur];
        const uint32_t* cB = (const uint32_t*)sB[cur];
#pragma unroll
        for (int kk = 0; kk < 2; kk++) {
            uint32_t af[4][4], bf[4][2];
#pragma unroll
            for (int i = 0; i < 4; i++) {
                const int r = wm * 64 + i * 16 + (lane >> 2);
                af[i][0] = cA[r * 20 + kk * 8 + (lane & 3)];
                af[i][1] = cA[(r + 8) * 20 + kk * 8 + (lane & 3)];
                af[i][2] = cA[r * 20 + kk * 8 + 4 + (lane & 3)];
                af[i][3] = cA[(r + 8) * 20 + kk * 8 + 4 + (lane & 3)];
            }
#pragma unroll
            for (int j = 0; j < 4; j++) {
                const int n = wn * 32 + j * 8 + (lane >> 2);
                bf[j][0] = cB[n * 20 + kk * 8 + (lane & 3)];
                bf[j][1] = cB[n * 20 + kk * 8 + 4 + (lane & 3)];
            }
#pragma unroll
            for (int i = 0; i < 4; i++)
#pragma unroll
                for (int j = 0; j < 4; j++)
                    mma_f16(acc[i][j], af[i], bf[j][0], bf[j][1]);
        }

        if (kt + 1 < nk) STS(cur ^ 1);
        __syncthreads();
    }

#pragma unroll
    for (int i = 0; i < 4; i++) {
#pragma unroll
        for (int j = 0; j < 4; j++) {
            const int row = bm + wm * 64 + i * 16 + (lane >> 2);
            const int col = bn + wn * 32 + j * 8 + (lane & 3) * 2;
            const float2 bv = *(const float2*)(bias + col);
#pragma unroll
            for (int hf = 0; hf < 2; hf++) {
                const int r = row + hf * 8;
                float vx = acc[i][j][hf * 2 + 0] + bv.x;
                float vy = acc[i][j][hf * 2 + 1] + bv.y;
                if (EPI == 1) {
                    float2 rv = *(const float2*)(res + (size_t)r * N + col);
                    vx += rv.x; vy += rv.y;
                }
                if (EPI == 2) { vx = fmaxf(vx, 0.f); vy = fmaxf(vy, 0.f); }
                if (OH) {
                    *(uint32_t*)(Ch + (size_t)r * N + col) = packh2(vx, vy);
                } else {
                    float2 o = { vx, vy };
                    *(float2*)(Cf + (size_t)r * N + col) = o;
                }
            }
        }
    }
}

// ---------------------------------------------------------------------------
// Transpose fp32 [K,N] -> fp16 [N,K]. block (32, 8). grid.z: head stacking.
// ---------------------------------------------------------------------------
__global__ void __launch_bounds__(256) transpose_h_kernel(
    const float* __restrict__ in, __half* __restrict__ out,
    int K, int N, long inz, long outz)
{
    __shared__ float t[32][33];
    in  += (size_t)blockIdx.z * inz;
    out += (size_t)blockIdx.z * outz;
    const int k0 = blockIdx.y * 32;
    const int n0 = blockIdx.x * 32;
#pragma unroll
    for (int i = 0; i < 32; i += 8)
        t[threadIdx.y + i][threadIdx.x] =
            in[(size_t)(k0 + threadIdx.y + i) * N + n0 + threadIdx.x];
    __syncthreads();
#pragma unroll
    for (int i = 0; i < 32; i += 8)
        out[(size_t)(n0 + threadIdx.y + i) * K + k0 + threadIdx.x] =
            __float2half_rn(t[threadIdx.x][threadIdx.y + i]);
}

// ---------------------------------------------------------------------------
// Flash attention, fp16 mma, FA2-style (P and stats in registers).
// CTA: 128 Q rows x 1 head, 8 warps (16 Q rows each), KV tile 64.
// Q fragments in registers; K in smem (stride 136h); V transposed in smem
// (stride 72h). All fragment LDS conflict-free per instruction.
// ---------------------------------------------------------------------------
#define QS_STR 136
#define KS_STR 136
#define VS_STR 72
#define FA_SMEM_BYTES ((128 * QS_STR + 64 * KS_STR + 128 * VS_STR) * 2)  // 70656

__global__ void __launch_bounds__(256) flash_attn_h_kernel(
    const __half* __restrict__ qb, const __half* __restrict__ kb,
    const __half* __restrict__ vb, __half* __restrict__ heads)
{
    extern __shared__ __half smh[];
    __half* Qs  = smh;
    __half* Ks  = Qs + 128 * QS_STR;
    __half* Vst = Ks + 64 * KS_STR;
    const uint32_t* Ks32  = (const uint32_t*)Ks;
    const uint32_t* Vst32 = (const uint32_t*)Vst;
    const uint32_t* Qs32  = (const uint32_t*)Qs;

    const int h   = blockIdx.y;
    const int q0  = blockIdx.x * 128;
    const int tid = threadIdx.x, lane = tid & 31, w = tid >> 5;
    const int rq = lane >> 2, kq = lane & 3;
    const float scale = 0.08838834764831845f;  // 1/sqrt(128)

    // load Q tile 128x128 halves
    {
        int idx = tid * 8;
#pragma unroll
        for (int it = 0; it < 8; it++) {
            int r = idx >> 7, c = idx & 127;
            *(uint4*)(Qs + r * QS_STR + c) =
                *(const uint4*)(qb + (size_t)(q0 + r) * D_DIM + h * 128 + c);
            idx += 2048;
        }
    }
    __syncthreads();

    // Q fragments -> registers (8 k16 steps)
    uint32_t qf[8][4];
    {
        const int r = w * 16 + rq;
#pragma unroll
        for (int ks = 0; ks < 8; ks++) {
            qf[ks][0] = Qs32[r * 68 + ks * 8 + kq];
            qf[ks][1] = Qs32[(r + 8) * 68 + ks * 8 + kq];
            qf[ks][2] = Qs32[r * 68 + ks * 8 + 4 + kq];
            qf[ks][3] = Qs32[(r + 8) * 68 + ks * 8 + 4 + kq];
        }
    }

    float O[16][4];
#pragma unroll
    for (int j = 0; j < 16; j++)
#pragma unroll
        for (int r = 0; r < 4; r++) O[j][r] = 0.f;
    float m0 = -1e30f, m1 = -1e30f, l0 = 0.f, l1 = 0.f;

    const int vr = tid & 63, vcb = (tid >> 6) * 8;

    for (int kblk = 0; kblk < 64; kblk++) {
        // K tile (64x128 halves, direct copy)
        {
            int idx = tid * 8;
#pragma unroll
            for (int it = 0; it < 4; it++) {
                int r = idx >> 7, c = idx & 127;
                *(uint4*)(Ks + r * KS_STR + c) =
                    *(const uint4*)(kb + (size_t)(kblk * 64 + r) * D_DIM + h * 128 + c);
                idx += 2048;
            }
        }
        // V tile transposed: Vst[hd][kv]
        {
#pragma unroll
            for (int it = 0; it < 4; it++) {
                int c = vcb + it * 32;
                uint4 u = *(const uint4*)(vb + (size_t)(kblk * 64 + vr) * D_DIM + h * 128 + c);
                const __half* hp = (const __half*)&u;
#pragma unroll
                for (int i = 0; i < 8; i++)
                    Vst[(c + i) * VS_STR + vr] = hp[i];
            }
        }
        __syncthreads();

        // S = Q @ K^T (warp tile 16 x 64)
        float facc[8][4];
#pragma unroll
        for (int j = 0; j < 8; j++)
#pragma unroll
            for (int r = 0; r < 4; r++) facc[j][r] = 0.f;
#pragma unroll
        for (int ks = 0; ks < 8; ks++) {
#pragma unroll
            for (int j = 0; j < 8; j++) {
                const int n = j * 8 + rq;
                uint32_t b0 = Ks32[n * 68 + ks * 8 + kq];
                uint32_t b1 = Ks32[n * 68 + ks * 8 + 4 + kq];
                mma_f16(facc[j], qf[ks], b0, b1);
            }
        }

        // online softmax in registers (quad-shuffle row reductions)
        float mx0 = -1e30f, mx1 = -1e30f;
#pragma unroll
        for (int j = 0; j < 8; j++) {
            facc[j][0] *= scale; facc[j][1] *= scale;
            facc[j][2] *= scale; facc[j][3] *= scale;
            mx0 = fmaxf(mx0, fmaxf(facc[j][0], facc[j][1]));
            mx1 = fmaxf(mx1, fmaxf(facc[j][2], facc[j][3]));
        }
        mx0 = fmaxf(mx0, __shfl_xor_sync(0xffffffffu, mx0, 1));
        mx0 = fmaxf(mx0, __shfl_xor_sync(0xffffffffu, mx0, 2));
        mx1 = fmaxf(mx1, __shfl_xor_sync(0xffffffffu, mx1, 1));
        mx1 = fmaxf(mx1, __shfl_xor_sync(0xffffffffu, mx1, 2));
        const float mn0 = fmaxf(m0, mx0), mn1 = fmaxf(m1, mx1);

        uint32_t ph0[8], ph1[8];
        float ls0 = 0.f, ls1 = 0.f;
#pragma unroll
        for (int j = 0; j < 8; j++) {
            float p0 = __expf(facc[j][0] - mn0);
            float p1 = __expf(facc[j][1] - mn0);
            float p2 = __expf(facc[j][2] - mn1);
            float p3 = __expf(facc[j][3] - mn1);
            ph0[j] = packh2(p0, p1);
            ph1[j] = packh2(p2, p3);
            ls0 += p0 + p1; ls1 += p2 + p3;
        }
        ls0 += __shfl_xor_sync(0xffffffffu, ls0, 1);
        ls0 += __shfl_xor_sync(0xffffffffu, ls0, 2);
        ls1 += __shfl_xor_sync(0xffffffffu, ls1, 1);
        ls1 += __shfl_xor_sync(0xffffffffu, ls1, 2);

        const float a0 = __expf(m0 - mn0), a1 = __expf(m1 - mn1);
        l0 = l0 * a0 + ls0; l1 = l1 * a1 + ls1;
        m0 = mn0; m1 = mn1;
#pragma unroll
        for (int j = 0; j < 16; j++) {
            O[j][0] *= a0; O[j][1] *= a0;
            O[j][2] *= a1; O[j][3] *= a1;
        }

        // O += P @ V  (P A-fragments straight from registers)
#pragma unroll
        for (int t = 0; t < 4; t++) {
            uint32_t af[4] = { ph0[2 * t], ph1[2 * t], ph0[2 * t + 1], ph1[2 * t + 1] };
#pragma unroll
            for (int j = 0; j < 16; j++) {
                const int n = j * 8 + rq;
                uint32_t b0 = Vst32[n * 36 + t * 8 + kq];
                uint32_t b1 = Vst32[n * 36 + t * 8 + 4 + kq];
                mma_f16(O[j], af, b0, b1);
            }
        }
        __syncthreads();
    }

    // normalize + write heads (half)
    {
        const float il0 = 1.f / l0, il1 = 1.f / l1;
        const int r = q0 + w * 16 + rq;
#pragma unroll
        for (int j = 0; j < 16; j++) {
            const int c = h * 128 + j * 8 + kq * 2;
            *(uint32_t*)(heads + (size_t)r * D_DIM + c) = packh2(O[j][0] * il0, O[j][1] * il0);
            *(uint32_t*)(heads + (size_t)(r + 8) * D_DIM + c) = packh2(O[j][2] * il1, O[j][3] * il1);
        }
    }
}

// ---------------------------------------------------------------------------
// LayerNorm over D=2048: fp32 in, fp16 out
// ---------------------------------------------------------------------------
__global__ void __launch_bounds__(256) layernorm_h_kernel(
    const float* __restrict__ in, const float* __restrict__ gamma,
    const float* __restrict__ beta, __half* __restrict__ out)
{
    __shared__ float red[16];
    const int row = blockIdx.x;
    const int tid = threadIdx.x;
    const float* rp = in + (size_t)row * D_DIM;

    float v[8];
    float s = 0.f, sq = 0.f;
#pragma unroll
    for (int it = 0; it < 2; ++it) {
        float4 t = *(const float4*)(rp + tid * 4 + it * 1024);
        v[it * 4 + 0] = t.x; v[it * 4 + 1] = t.y;
        v[it * 4 + 2] = t.z; v[it * 4 + 3] = t.w;
    }
#pragma unroll
    for (int i = 0; i < 8; i++) { s += v[i]; sq += v[i] * v[i]; }
#pragma unroll
    for (int o = 16; o > 0; o >>= 1) {
        s  += __shfl_xor_sync(0xffffffffu, s, o);
        sq += __shfl_xor_sync(0xffffffffu, sq, o);
    }
    if ((tid & 31) == 0) { red[tid >> 5] = s; red[8 + (tid >> 5)] = sq; }
    __syncthreads();
    if (tid < 32) {
        float ss = (tid < 8) ? red[tid] : 0.f;
        float qq = (tid < 8) ? red[8 + tid] : 0.f;
#pragma unroll
        for (int o = 4; o > 0; o >>= 1) {
            ss += __shfl_xor_sync(0xffffffffu, ss, o);
            qq += __shfl_xor_sync(0xffffffffu, qq, o);
        }
        if (tid == 0) { red[0] = ss; red[1] = qq; }
    }
    __syncthreads();
    const float mu  = red[0] * (1.f / D_DIM);
    const float var = red[1] * (1.f / D_DIM) - mu * mu;
    const float rs  = rsqrtf(var + 1e-5f);
#pragma unroll
    for (int it = 0; it < 2; ++it) {
        const int c = tid * 4 + it * 1024;
        float4 g = *(const float4*)(gamma + c);
        float4 b = *(const float4*)(beta + c);
        uint2 o;
        o.x = packh2((v[it * 4 + 0] - mu) * rs * g.x + b.x,
                     (v[it * 4 + 1] - mu) * rs * g.y + b.y);
        o.y = packh2((v[it * 4 + 2] - mu) * rs * g.z + b.z,
                     (v[it * 4 + 3] - mu) * rs * g.w + b.w);
        *(uint2*)(out + (size_t)row * D_DIM + c) = o;
    }
}

// ---------------------------------------------------------------------------
// Launch
// ---------------------------------------------------------------------------
extern "C" void kernel_launch(void* const* d_in, const int* in_sizes, int n_in,
                              void* d_out, int out_size)
{
    const float* x     = (const float*)d_in[0];
    const float* Wq    = (const float*)d_in[1];
    const float* bq    = (const float*)d_in[2];
    const float* Wk    = (const float*)d_in[3];
    const float* bk    = (const float*)d_in[4];
    const float* Wv    = (const float*)d_in[5];
    const float* bv    = (const float*)d_in[6];
    const float* Wp    = (const float*)d_in[7];
    const float* bp    = (const float*)d_in[8];
    const float* W1    = (const float*)d_in[9];
    const float* b1    = (const float*)d_in[10];
    const float* W2    = (const float*)d_in[11];
    const float* b2    = (const float*)d_in[12];
    const float* gamma = (const float*)d_in[13];
    const float* beta  = (const float*)d_in[14];
    float* out = (float*)d_out;

    __half *q, *k, *v, *heads, *ln, *h1;
    float *proj;
    __half *wqt, *wkt, *wvt, *wpt, *w1t, *w2t;
    cudaGetSymbolAddress((void**)&q,     g_qh);
    cudaGetSymbolAddress((void**)&k,     g_kh);
    cudaGetSymbolAddress((void**)&v,     g_vh);
    cudaGetSymbolAddress((void**)&heads, g_headsh);
    cudaGetSymbolAddress((void**)&proj,  g_proj);
    cudaGetSymbolAddress((void**)&ln,    g_lnh);
    cudaGetSymbolAddress((void**)&h1,    g_h1h);
    cudaGetSymbolAddress((void**)&wqt,   g_wqt);
    cudaGetSymbolAddress((void**)&wkt,   g_wkt);
    cudaGetSymbolAddress((void**)&wvt,   g_wvt);
    cudaGetSymbolAddress((void**)&wpt,   g_wpt);
    cudaGetSymbolAddress((void**)&w1t,   g_w1t);
    cudaGetSymbolAddress((void**)&w2t,   g_w2t);

    // ---- weight transposes to fp16 [N, K] ----
    const dim3 tb(32, 8);
    transpose_h_kernel<<<dim3(4, 64, 16), tb>>>(Wq, wqt, D_DIM, 128, (long)D_DIM * 128, (long)128 * D_DIM);
    transpose_h_kernel<<<dim3(4, 64, 16), tb>>>(Wk, wkt, D_DIM, 128, (long)D_DIM * 128, (long)128 * D_DIM);
    transpose_h_kernel<<<dim3(4, 64, 16), tb>>>(Wv, wvt, D_DIM, 128, (long)D_DIM * 128, (long)128 * D_DIM);
    transpose_h_kernel<<<dim3(64, 64, 1),  tb>>>(Wp, wpt, D_DIM, D_DIM, 0, 0);
    transpose_h_kernel<<<dim3(256, 64, 1), tb>>>(W1, w1t, D_DIM, F_DIM, 0, 0);
    transpose_h_kernel<<<dim3(64, 256, 1), tb>>>(W2, w2t, F_DIM, D_DIM, 0, 0);

    const dim3 blk(256);
    const dim3 g_dd(D_DIM / 128, S_LEN / 128);   // (16, 32)
    const dim3 g_f1(F_DIM / 128, S_LEN / 128);   // (64, 32)

    // QKV projections: fp32 A, half out
    gemm_h_kernel<0, 0, 1><<<g_dd, blk>>>(x, wqt, bq, nullptr, q, S_LEN, D_DIM, D_DIM);
    gemm_h_kernel<0, 0, 1><<<g_dd, blk>>>(x, wkt, bk, nullptr, k, S_LEN, D_DIM, D_DIM);
    gemm_h_kernel<0, 0, 1><<<g_dd, blk>>>(x, wvt, bv, nullptr, v, S_LEN, D_DIM, D_DIM);

    // flash attention (fp16 mma)
    cudaFuncSetAttribute(flash_attn_h_kernel,
                         cudaFuncAttributeMaxDynamicSharedMemorySize, FA_SMEM_BYTES);
    flash_attn_h_kernel<<<dim3(S_LEN / 128, H_NUM), blk, FA_SMEM_BYTES>>>(q, k, v, heads);

    // output projection + residual (fp32 out), LayerNorm (half out)
    gemm_h_kernel<1, 1, 0><<<g_dd, blk>>>(heads, wpt, bp, x, proj, S_LEN, D_DIM, D_DIM);
    layernorm_h_kernel<<<S_LEN, blk>>>(proj, gamma, beta, ln);

    // FFN
    gemm_h_kernel<2, 1, 1><<<g_f1, blk>>>(ln, w1t, b1, nullptr, h1, S_LEN, F_DIM, D_DIM);
    gemm_h_kernel<0, 1, 0><<<g_dd, blk>>>(h1, w2t, b2, nullptr, out, S_LEN, D_DIM, F_DIM);
}

// round 6
// speedup vs baseline: 6.9566x; 1.3397x over previous
#include <cuda_runtime.h>
#include <cuda_fp16.h>
#include <cstdint>

// Problem dims
#define S_LEN 4096
#define D_DIM 2048
#define H_NUM 16
#define F_DIM 8192

// ---------------------------------------------------------------------------
// Scratch (allocation is banned; use device globals)
// ---------------------------------------------------------------------------
__device__ __half g_xh[S_LEN * D_DIM];
__device__ __half g_qh[S_LEN * D_DIM];
__device__ __half g_kh[S_LEN * D_DIM];
__device__ __half g_vh[S_LEN * D_DIM];
__device__ __half g_headsh[S_LEN * D_DIM];
__device__ float  g_proj[S_LEN * D_DIM];
__device__ __half g_lnh[S_LEN * D_DIM];
__device__ __half g_h1h[S_LEN * F_DIM];
// transposed fp16 weights, [N, K] row-major
__device__ __half g_wqt[D_DIM * D_DIM];
__device__ __half g_wkt[D_DIM * D_DIM];
__device__ __half g_wvt[D_DIM * D_DIM];
__device__ __half g_wpt[D_DIM * D_DIM];
__device__ __half g_w1t[F_DIM * D_DIM];
__device__ __half g_w2t[D_DIM * F_DIM];

// ---------------------------------------------------------------------------
// Portable PTX helpers (sm_80-level; tcgen05 is gated off on plain sm_103)
// ---------------------------------------------------------------------------
__device__ __forceinline__ uint32_t smem_u32(const void* p) {
    uint32_t a;
    asm("{ .reg .u64 t; cvta.to.shared.u64 t, %1; cvt.u32.u64 %0, t; }"
        : "=r"(a) : "l"(p));
    return a;
}

__device__ __forceinline__ uint32_t packh2(float a, float b) {
    __half2 h = __floats2half2_rn(a, b);
    return *reinterpret_cast<uint32_t*>(&h);
}

__device__ __forceinline__ void mma_f16(float* c, const uint32_t* a,
                                        uint32_t b0, uint32_t b1) {
    asm volatile(
        "mma.sync.aligned.m16n8k16.row.col.f32.f16.f16.f32 "
        "{%0,%1,%2,%3}, {%4,%5,%6,%7}, {%8,%9}, {%0,%1,%2,%3};"
        : "+f"(c[0]), "+f"(c[1]), "+f"(c[2]), "+f"(c[3])
        : "r"(a[0]), "r"(a[1]), "r"(a[2]), "r"(a[3]), "r"(b0), "r"(b1));
}

__device__ __forceinline__ void cp16(uint32_t saddr, const void* g) {
    asm volatile("cp.async.ca.shared.global [%0], [%1], 16;" :: "r"(saddr), "l"(g));
}
__device__ __forceinline__ void cp_commit() {
    asm volatile("cp.async.commit_group;" ::: "memory");
}
template <int N>
__device__ __forceinline__ void cp_wait() {
    asm volatile("cp.async.wait_group %0;" :: "n"(N) : "memory");
}

__device__ __forceinline__ void ldm_x4(uint32_t* r, uint32_t addr) {
    asm volatile("ldmatrix.sync.aligned.m8n8.x4.shared.b16 {%0,%1,%2,%3}, [%4];"
        : "=r"(r[0]), "=r"(r[1]), "=r"(r[2]), "=r"(r[3]) : "r"(addr));
}

// ---------------------------------------------------------------------------
// fp16 warp-MMA GEMM, cp.async 3-stage + ldmatrix fragments.
// C[M,N] = A[M,K] @ Bt[N,K]^T + epilogue. A is fp16.
// CTA 128x128, BK=32 halves, 256 threads = 8 warps (2Mx4N), warp 64x32.
//   EPI 0: +bias   EPI 1: +bias+res(fp32)   EPI 2: relu(+bias)
//   OH: 1 -> half output, 0 -> fp32 output
// smem row stride 40 halves (80B): conflict-free for ldmatrix (8 row addrs
// at 80r mod 128 = {0,80,32,112,64,16,96,48}, all distinct 16B slots).
// ---------------------------------------------------------------------------
#define GSTR 40
#define STAGE_HALVES (2 * 128 * GSTR)          // A + B per stage
#define GEMM_SMEM_BYTES (3 * STAGE_HALVES * 2) // 61440

template <int EPI, int OH>
__global__ void __launch_bounds__(256) gemm_h_kernel(
    const __half* __restrict__ A, const __half* __restrict__ Bt,
    const float* __restrict__ bias, const float* __restrict__ res,
    void* __restrict__ Cv, int M, int N, int K)
{
    extern __shared__ __half sh[];
    const uint32_t sbase = smem_u32(sh);

    float*  Cf = (float*)Cv;
    __half* Ch = (__half*)Cv;

    const int tid = threadIdx.x, lane = tid & 31, w = tid >> 5;
    const int wm = w >> 2, wn = w & 3;
    const int bm = blockIdx.y * 128, bn = blockIdx.x * 128;
    const int nk = K >> 5;

    // cp.async mapping: 128 rows x 4 chunks(16B) per operand; 2 per thread
    const int crow = tid >> 2;
    const int ccol = (tid & 3) * 8;   // halves

    auto load_stage = [&](int kt, int slot) {
        const int k0 = kt << 5;
        const uint32_t sa = sbase + slot * STAGE_HALVES * 2;
        const uint32_t sb = sa + 128 * GSTR * 2;
#pragma unroll
        for (int it = 0; it < 2; it++) {
            const int r = crow + it * 64;
            cp16(sa + (r * GSTR + ccol) * 2, A  + (size_t)(bm + r) * K + k0 + ccol);
            cp16(sb + (r * GSTR + ccol) * 2, Bt + (size_t)(bn + r) * K + k0 + ccol);
        }
    };

    float acc[4][4][4];
#pragma unroll
    for (int i = 0; i < 4; i++)
#pragma unroll
        for (int j = 0; j < 4; j++)
#pragma unroll
            for (int r = 0; r < 4; r++) acc[i][j][r] = 0.f;

    load_stage(0, 0); cp_commit();
    load_stage(1, 1); cp_commit();

    const int frow = lane & 15;          // ldmatrix row-within-16
    const int fcol = (lane >> 4) * 8;    // ldmatrix k-half select

    for (int kt = 0; kt < nk; kt++) {
        cp_wait<1>();
        __syncthreads();

        const int slot = kt - (kt / 3) * 3;
        const uint32_t sa = sbase + slot * STAGE_HALVES * 2;
        const uint32_t sb = sa + 128 * GSTR * 2;

#pragma unroll
        for (int kk = 0; kk < 2; kk++) {
            uint32_t af[4][4], bf[2][4];
#pragma unroll
            for (int i = 0; i < 4; i++)
                ldm_x4(af[i], sa + ((wm * 64 + i * 16 + frow) * GSTR + kk * 16 + fcol) * 2);
#pragma unroll
            for (int j = 0; j < 2; j++)
                ldm_x4(bf[j], sb + ((wn * 32 + j * 16 + frow) * GSTR + kk * 16 + fcol) * 2);
#pragma unroll
            for (int i = 0; i < 4; i++)
#pragma unroll
                for (int j = 0; j < 4; j++)
                    mma_f16(acc[i][j], af[i], bf[j >> 1][j & 1], bf[j >> 1][2 + (j & 1)]);
        }

        if (kt + 2 < nk) load_stage(kt + 2, (kt + 2) - ((kt + 2) / 3) * 3);
        cp_commit();
    }

    // epilogue
#pragma unroll
    for (int i = 0; i < 4; i++) {
#pragma unroll
        for (int j = 0; j < 4; j++) {
            const int row = bm + wm * 64 + i * 16 + (lane >> 2);
            const int col = bn + wn * 32 + j * 8 + (lane & 3) * 2;
            const float2 bv = *(const float2*)(bias + col);
#pragma unroll
            for (int hf = 0; hf < 2; hf++) {
                const int r = row + hf * 8;
                float vx = acc[i][j][hf * 2 + 0] + bv.x;
                float vy = acc[i][j][hf * 2 + 1] + bv.y;
                if (EPI == 1) {
                    float2 rv = *(const float2*)(res + (size_t)r * N + col);
                    vx += rv.x; vy += rv.y;
                }
                if (EPI == 2) { vx = fmaxf(vx, 0.f); vy = fmaxf(vy, 0.f); }
                if (OH) {
                    *(uint32_t*)(Ch + (size_t)r * N + col) = packh2(vx, vy);
                } else {
                    float2 o = { vx, vy };
                    *(float2*)(Cf + (size_t)r * N + col) = o;
                }
            }
        }
    }
}

// ---------------------------------------------------------------------------
// fp32 -> fp16 bulk convert (x), 8 elems/thread
// ---------------------------------------------------------------------------
__global__ void __launch_bounds__(256) f2h_kernel(
    const float* __restrict__ in, __half* __restrict__ out)
{
    const size_t i = ((size_t)blockIdx.x * 256 + threadIdx.x) * 8;
    float4 a = *(const float4*)(in + i);
    float4 b = *(const float4*)(in + i + 4);
    uint4 o;
    o.x = packh2(a.x, a.y); o.y = packh2(a.z, a.w);
    o.z = packh2(b.x, b.y); o.w = packh2(b.z, b.w);
    *(uint4*)(out + i) = o;
}

// ---------------------------------------------------------------------------
// Transpose fp32 [K,N] -> fp16 [N,K]. block (32, 8). grid.z: head stacking.
// ---------------------------------------------------------------------------
__global__ void __launch_bounds__(256) transpose_h_kernel(
    const float* __restrict__ in, __half* __restrict__ out,
    int K, int N, long inz, long outz)
{
    __shared__ float t[32][33];
    in  += (size_t)blockIdx.z * inz;
    out += (size_t)blockIdx.z * outz;
    const int k0 = blockIdx.y * 32;
    const int n0 = blockIdx.x * 32;
#pragma unroll
    for (int i = 0; i < 32; i += 8)
        t[threadIdx.y + i][threadIdx.x] =
            in[(size_t)(k0 + threadIdx.y + i) * N + n0 + threadIdx.x];
    __syncthreads();
#pragma unroll
    for (int i = 0; i < 32; i += 8)
        out[(size_t)(n0 + threadIdx.y + i) * K + k0 + threadIdx.x] =
            __float2half_rn(t[threadIdx.x][threadIdx.y + i]);
}

// ---------------------------------------------------------------------------
// Flash attention, fp16 mma, FA2-style (unchanged round-5 version)
// ---------------------------------------------------------------------------
#define QS_STR 136
#define KS_STR 136
#define VS_STR 72
#define FA_SMEM_BYTES ((128 * QS_STR + 64 * KS_STR + 128 * VS_STR) * 2)  // 70656

__global__ void __launch_bounds__(256) flash_attn_h_kernel(
    const __half* __restrict__ qb, const __half* __restrict__ kb,
    const __half* __restrict__ vb, __half* __restrict__ heads)
{
    extern __shared__ __half smh[];
    __half* Qs  = smh;
    __half* Ks  = Qs + 128 * QS_STR;
    __half* Vst = Ks + 64 * KS_STR;
    const uint32_t* Ks32  = (const uint32_t*)Ks;
    const uint32_t* Vst32 = (const uint32_t*)Vst;
    const uint32_t* Qs32  = (const uint32_t*)Qs;

    const int h   = blockIdx.y;
    const int q0  = blockIdx.x * 128;
    const int tid = threadIdx.x, lane = tid & 31, w = tid >> 5;
    const int rq = lane >> 2, kq = lane & 3;
    const float scale = 0.08838834764831845f;

    {
        int idx = tid * 8;
#pragma unroll
        for (int it = 0; it < 8; it++) {
            int r = idx >> 7, c = idx & 127;
            *(uint4*)(Qs + r * QS_STR + c) =
                *(const uint4*)(qb + (size_t)(q0 + r) * D_DIM + h * 128 + c);
            idx += 2048;
        }
    }
    __syncthreads();

    uint32_t qf[8][4];
    {
        const int r = w * 16 + rq;
#pragma unroll
        for (int ks = 0; ks < 8; ks++) {
            qf[ks][0] = Qs32[r * 68 + ks * 8 + kq];
            qf[ks][1] = Qs32[(r + 8) * 68 + ks * 8 + kq];
            qf[ks][2] = Qs32[r * 68 + ks * 8 + 4 + kq];
            qf[ks][3] = Qs32[(r + 8) * 68 + ks * 8 + 4 + kq];
        }
    }

    float O[16][4];
#pragma unroll
    for (int j = 0; j < 16; j++)
#pragma unroll
        for (int r = 0; r < 4; r++) O[j][r] = 0.f;
    float m0 = -1e30f, m1 = -1e30f, l0 = 0.f, l1 = 0.f;

    const int vr = tid & 63, vcb = (tid >> 6) * 8;

    for (int kblk = 0; kblk < 64; kblk++) {
        {
            int idx = tid * 8;
#pragma unroll
            for (int it = 0; it < 4; it++) {
                int r = idx >> 7, c = idx & 127;
                *(uint4*)(Ks + r * KS_STR + c) =
                    *(const uint4*)(kb + (size_t)(kblk * 64 + r) * D_DIM + h * 128 + c);
                idx += 2048;
            }
        }
        {
#pragma unroll
            for (int it = 0; it < 4; it++) {
                int c = vcb + it * 32;
                uint4 u = *(const uint4*)(vb + (size_t)(kblk * 64 + vr) * D_DIM + h * 128 + c);
                const __half* hp = (const __half*)&u;
#pragma unroll
                for (int i = 0; i < 8; i++)
                    Vst[(c + i) * VS_STR + vr] = hp[i];
            }
        }
        __syncthreads();

        float facc[8][4];
#pragma unroll
        for (int j = 0; j < 8; j++)
#pragma unroll
            for (int r = 0; r < 4; r++) facc[j][r] = 0.f;
#pragma unroll
        for (int ks = 0; ks < 8; ks++) {
#pragma unroll
            for (int j = 0; j < 8; j++) {
                const int n = j * 8 + rq;
                uint32_t b0 = Ks32[n * 68 + ks * 8 + kq];
                uint32_t b1 = Ks32[n * 68 + ks * 8 + 4 + kq];
                mma_f16(facc[j], qf[ks], b0, b1);
            }
        }

        float mx0 = -1e30f, mx1 = -1e30f;
#pragma unroll
        for (int j = 0; j < 8; j++) {
            facc[j][0] *= scale; facc[j][1] *= scale;
            facc[j][2] *= scale; facc[j][3] *= scale;
            mx0 = fmaxf(mx0, fmaxf(facc[j][0], facc[j][1]));
            mx1 = fmaxf(mx1, fmaxf(facc[j][2], facc[j][3]));
        }
        mx0 = fmaxf(mx0, __shfl_xor_sync(0xffffffffu, mx0, 1));
        mx0 = fmaxf(mx0, __shfl_xor_sync(0xffffffffu, mx0, 2));
        mx1 = fmaxf(mx1, __shfl_xor_sync(0xffffffffu, mx1, 1));
        mx1 = fmaxf(mx1, __shfl_xor_sync(0xffffffffu, mx1, 2));
        const float mn0 = fmaxf(m0, mx0), mn1 = fmaxf(m1, mx1);

        uint32_t ph0[8], ph1[8];
        float ls0 = 0.f, ls1 = 0.f;
#pragma unroll
        for (int j = 0; j < 8; j++) {
            float p0 = __expf(facc[j][0] - mn0);
            float p1 = __expf(facc[j][1] - mn0);
            float p2 = __expf(facc[j][2] - mn1);
            float p3 = __expf(facc[j][3] - mn1);
            ph0[j] = packh2(p0, p1);
            ph1[j] = packh2(p2, p3);
            ls0 += p0 + p1; ls1 += p2 + p3;
        }
        ls0 += __shfl_xor_sync(0xffffffffu, ls0, 1);
        ls0 += __shfl_xor_sync(0xffffffffu, ls0, 2);
        ls1 += __shfl_xor_sync(0xffffffffu, ls1, 1);
        ls1 += __shfl_xor_sync(0xffffffffu, ls1, 2);

        const float a0 = __expf(m0 - mn0), a1 = __expf(m1 - mn1);
        l0 = l0 * a0 + ls0; l1 = l1 * a1 + ls1;
        m0 = mn0; m1 = mn1;
#pragma unroll
        for (int j = 0; j < 16; j++) {
            O[j][0] *= a0; O[j][1] *= a0;
            O[j][2] *= a1; O[j][3] *= a1;
        }

#pragma unroll
        for (int t = 0; t < 4; t++) {
            uint32_t af[4] = { ph0[2 * t], ph1[2 * t], ph0[2 * t + 1], ph1[2 * t + 1] };
#pragma unroll
            for (int j = 0; j < 16; j++) {
                const int n = j * 8 + rq;
                uint32_t b0 = Vst32[n * 36 + t * 8 + kq];
                uint32_t b1 = Vst32[n * 36 + t * 8 + 4 + kq];
                mma_f16(O[j], af, b0, b1);
            }
        }
        __syncthreads();
    }

    {
        const float il0 = 1.f / l0, il1 = 1.f / l1;
        const int r = q0 + w * 16 + rq;
#pragma unroll
        for (int j = 0; j < 16; j++) {
            const int c = h * 128 + j * 8 + kq * 2;
            *(uint32_t*)(heads + (size_t)r * D_DIM + c) = packh2(O[j][0] * il0, O[j][1] * il0);
            *(uint32_t*)(heads + (size_t)(r + 8) * D_DIM + c) = packh2(O[j][2] * il1, O[j][3] * il1);
        }
    }
}

// ---------------------------------------------------------------------------
// LayerNorm over D=2048: fp32 in, fp16 out
// ---------------------------------------------------------------------------
__global__ void __launch_bounds__(256) layernorm_h_kernel(
    const float* __restrict__ in, const float* __restrict__ gamma,
    const float* __restrict__ beta, __half* __restrict__ out)
{
    __shared__ float red[16];
    const int row = blockIdx.x;
    const int tid = threadIdx.x;
    const float* rp = in + (size_t)row * D_DIM;

    float v[8];
    float s = 0.f, sq = 0.f;
#pragma unroll
    for (int it = 0; it < 2; ++it) {
        float4 t = *(const float4*)(rp + tid * 4 + it * 1024);
        v[it * 4 + 0] = t.x; v[it * 4 + 1] = t.y;
        v[it * 4 + 2] = t.z; v[it * 4 + 3] = t.w;
    }
#pragma unroll
    for (int i = 0; i < 8; i++) { s += v[i]; sq += v[i] * v[i]; }
#pragma unroll
    for (int o = 16; o > 0; o >>= 1) {
        s  += __shfl_xor_sync(0xffffffffu, s, o);
        sq += __shfl_xor_sync(0xffffffffu, sq, o);
    }
    if ((tid & 31) == 0) { red[tid >> 5] = s; red[8 + (tid >> 5)] = sq; }
    __syncthreads();
    if (tid < 32) {
        float ss = (tid < 8) ? red[tid] : 0.f;
        float qq = (tid < 8) ? red[8 + tid] : 0.f;
#pragma unroll
        for (int o = 4; o > 0; o >>= 1) {
            ss += __shfl_xor_sync(0xffffffffu, ss, o);
            qq += __shfl_xor_sync(0xffffffffu, qq, o);
        }
        if (tid == 0) { red[0] = ss; red[1] = qq; }
    }
    __syncthreads();
    const float mu  = red[0] * (1.f / D_DIM);
    const float var = red[1] * (1.f / D_DIM) - mu * mu;
    const float rs  = rsqrtf(var + 1e-5f);
#pragma unroll
    for (int it = 0; it < 2; ++it) {
        const int c = tid * 4 + it * 1024;
        float4 g = *(const float4*)(gamma + c);
        float4 b = *(const float4*)(beta + c);
        uint2 o;
        o.x = packh2((v[it * 4 + 0] - mu) * rs * g.x + b.x,
                     (v[it * 4 + 1] - mu) * rs * g.y + b.y);
        o.y = packh2((v[it * 4 + 2] - mu) * rs * g.z + b.z,
                     (v[it * 4 + 3] - mu) * rs * g.w + b.w);
        *(uint2*)(out + (size_t)row * D_DIM + c) = o;
    }
}

// ---------------------------------------------------------------------------
// Launch
// ---------------------------------------------------------------------------
extern "C" void kernel_launch(void* const* d_in, const int* in_sizes, int n_in,
                              void* d_out, int out_size)
{
    const float* x     = (const float*)d_in[0];
    const float* Wq    = (const float*)d_in[1];
    const float* bq    = (const float*)d_in[2];
    const float* Wk    = (const float*)d_in[3];
    const float* bk    = (const float*)d_in[4];
    const float* Wv    = (const float*)d_in[5];
    const float* bv    = (const float*)d_in[6];
    const float* Wp    = (const float*)d_in[7];
    const float* bp    = (const float*)d_in[8];
    const float* W1    = (const float*)d_in[9];
    const float* b1    = (const float*)d_in[10];
    const float* W2    = (const float*)d_in[11];
    const float* b2    = (const float*)d_in[12];
    const float* gamma = (const float*)d_in[13];
    const float* beta  = (const float*)d_in[14];
    float* out = (float*)d_out;

    __half *xh, *q, *k, *v, *heads, *ln, *h1;
    float *proj;
    __half *wqt, *wkt, *wvt, *wpt, *w1t, *w2t;
    cudaGetSymbolAddress((void**)&xh,    g_xh);
    cudaGetSymbolAddress((void**)&q,     g_qh);
    cudaGetSymbolAddress((void**)&k,     g_kh);
    cudaGetSymbolAddress((void**)&v,     g_vh);
    cudaGetSymbolAddress((void**)&heads, g_headsh);
    cudaGetSymbolAddress((void**)&proj,  g_proj);
    cudaGetSymbolAddress((void**)&ln,    g_lnh);
    cudaGetSymbolAddress((void**)&h1,    g_h1h);
    cudaGetSymbolAddress((void**)&wqt,   g_wqt);
    cudaGetSymbolAddress((void**)&wkt,   g_wkt);
    cudaGetSymbolAddress((void**)&wvt,   g_wvt);
    cudaGetSymbolAddress((void**)&wpt,   g_wpt);
    cudaGetSymbolAddress((void**)&w1t,   g_w1t);
    cudaGetSymbolAddress((void**)&w2t,   g_w2t);

    // ---- x -> fp16, weight transposes to fp16 [N, K] ----
    f2h_kernel<<<S_LEN * D_DIM / (256 * 8), 256>>>(x, xh);
    const dim3 tb(32, 8);
    transpose_h_kernel<<<dim3(4, 64, 16), tb>>>(Wq, wqt, D_DIM, 128, (long)D_DIM * 128, (long)128 * D_DIM);
    transpose_h_kernel<<<dim3(4, 64, 16), tb>>>(Wk, wkt, D_DIM, 128, (long)D_DIM * 128, (long)128 * D_DIM);
    transpose_h_kernel<<<dim3(4, 64, 16), tb>>>(Wv, wvt, D_DIM, 128, (long)D_DIM * 128, (long)128 * D_DIM);
    transpose_h_kernel<<<dim3(64, 64, 1),  tb>>>(Wp, wpt, D_DIM, D_DIM, 0, 0);
    transpose_h_kernel<<<dim3(256, 64, 1), tb>>>(W1, w1t, D_DIM, F_DIM, 0, 0);
    transpose_h_kernel<<<dim3(64, 256, 1), tb>>>(W2, w2t, F_DIM, D_DIM, 0, 0);

    cudaFuncSetAttribute(gemm_h_kernel<0, 1>, cudaFuncAttributeMaxDynamicSharedMemorySize, GEMM_SMEM_BYTES);
    cudaFuncSetAttribute(gemm_h_kernel<1, 0>, cudaFuncAttributeMaxDynamicSharedMemorySize, GEMM_SMEM_BYTES);
    cudaFuncSetAttribute(gemm_h_kernel<2, 1>, cudaFuncAttributeMaxDynamicSharedMemorySize, GEMM_SMEM_BYTES);
    cudaFuncSetAttribute(gemm_h_kernel<0, 0>, cudaFuncAttributeMaxDynamicSharedMemorySize, GEMM_SMEM_BYTES);

    const dim3 blk(256);
    const dim3 g_dd(D_DIM / 128, S_LEN / 128);   // (16, 32)
    const dim3 g_f1(F_DIM / 128, S_LEN / 128);   // (64, 32)

    // QKV projections
    gemm_h_kernel<0, 1><<<g_dd, blk, GEMM_SMEM_BYTES>>>(xh, wqt, bq, nullptr, q, S_LEN, D_DIM, D_DIM);
    gemm_h_kernel<0, 1><<<g_dd, blk, GEMM_SMEM_BYTES>>>(xh, wkt, bk, nullptr, k, S_LEN, D_DIM, D_DIM);
    gemm_h_kernel<0, 1><<<g_dd, blk, GEMM_SMEM_BYTES>>>(xh, wvt, bv, nullptr, v, S_LEN, D_DIM, D_DIM);

    // flash attention
    cudaFuncSetAttribute(flash_attn_h_kernel,
                         cudaFuncAttributeMaxDynamicSharedMemorySize, FA_SMEM_BYTES);
    flash_attn_h_kernel<<<dim3(S_LEN / 128, H_NUM), blk, FA_SMEM_BYTES>>>(q, k, v, heads);

    // output projection + residual (fp32 x), LayerNorm
    gemm_h_kernel<1, 0><<<g_dd, blk, GEMM_SMEM_BYTES>>>(heads, wpt, bp, x, proj, S_LEN, D_DIM, D_DIM);
    layernorm_h_kernel<<<S_LEN, blk>>>(proj, gamma, beta, ln);

    // FFN
    gemm_h_kernel<2, 1><<<g_f1, blk, GEMM_SMEM_BYTES>>>(ln, w1t, b1, nullptr, h1, S_LEN, F_DIM, D_DIM);
    gemm_h_kernel<0, 0><<<g_dd, blk, GEMM_SMEM_BYTES>>>(h1, w2t, b2, nullptr, out, S_LEN, D_DIM, F_DIM);
}